// round 3
// baseline (speedup 1.0000x reference)
#include <cuda_runtime.h>

#define BB 2
#define SS 2048
#define DD 512
#define HH 8

// Scratch (allocation-free: __device__ globals)
__device__ float g_Qh[BB * SS * DD];
__device__ float g_Kh[BB * SS * DD];
__device__ float g_Vh[BB * SS * DD];
__device__ float g_ctx[BB * SS * DD];

// ---------------------------------------------------------------------------
// GEMM: C[M,N] = A[M,K] @ W[K,N] + bias[N]
// BM=128, BN=128, BK=16. 256 threads, 8x8 micro-tile, register prefetch.
// ---------------------------------------------------------------------------
__global__ __launch_bounds__(256)
void gemm_bias_kernel(const float* __restrict__ A, const float* __restrict__ W,
                      const float* __restrict__ bias, float* __restrict__ C,
                      int M, int N, int K) {
    __shared__ float As[16][132];   // As[k][m]
    __shared__ float Ws[16][128];   // Ws[k][n]

    const int tid = threadIdx.x;
    const int ty = tid >> 4;
    const int tx = tid & 15;
    const int m0 = blockIdx.x * 128;
    const int n0 = blockIdx.y * 128;

    float acc[8][8];
    const float4 b0 = *reinterpret_cast<const float4*>(bias + n0 + tx * 8);
    const float4 b1 = *reinterpret_cast<const float4*>(bias + n0 + tx * 8 + 4);
#pragma unroll
    for (int i = 0; i < 8; i++) {
        acc[i][0] = b0.x; acc[i][1] = b0.y; acc[i][2] = b0.z; acc[i][3] = b0.w;
        acc[i][4] = b1.x; acc[i][5] = b1.y; acc[i][6] = b1.z; acc[i][7] = b1.w;
    }

    float4 pa[2], pw[2];
#pragma unroll
    for (int t = 0; t < 2; t++) {
        int idx = tid + t * 256;
        int r = idx >> 2, k4 = idx & 3;
        pa[t] = *reinterpret_cast<const float4*>(A + (size_t)(m0 + r) * K + k4 * 4);
        int kk = idx >> 5, c4 = idx & 31;
        pw[t] = *reinterpret_cast<const float4*>(W + (size_t)kk * N + n0 + c4 * 4);
    }

    for (int k0 = 0; k0 < K; k0 += 16) {
        __syncthreads();
#pragma unroll
        for (int t = 0; t < 2; t++) {
            int idx = tid + t * 256;
            int r = idx >> 2, k4 = idx & 3;
            As[k4 * 4 + 0][r] = pa[t].x;
            As[k4 * 4 + 1][r] = pa[t].y;
            As[k4 * 4 + 2][r] = pa[t].z;
            As[k4 * 4 + 3][r] = pa[t].w;
            int kk = idx >> 5, c4 = idx & 31;
            *reinterpret_cast<float4*>(&Ws[kk][c4 * 4]) = pw[t];
        }
        __syncthreads();

        if (k0 + 16 < K) {
#pragma unroll
            for (int t = 0; t < 2; t++) {
                int idx = tid + t * 256;
                int r = idx >> 2, k4 = idx & 3;
                pa[t] = *reinterpret_cast<const float4*>(
                    A + (size_t)(m0 + r) * K + k0 + 16 + k4 * 4);
                int kk = idx >> 5, c4 = idx & 31;
                pw[t] = *reinterpret_cast<const float4*>(
                    W + (size_t)(k0 + 16 + kk) * N + n0 + c4 * 4);
            }
        }

#pragma unroll
        for (int k = 0; k < 16; k++) {
            float4 a0 = *reinterpret_cast<const float4*>(&As[k][ty * 8]);
            float4 a1 = *reinterpret_cast<const float4*>(&As[k][ty * 8 + 4]);
            float4 w0 = *reinterpret_cast<const float4*>(&Ws[k][tx * 8]);
            float4 w1 = *reinterpret_cast<const float4*>(&Ws[k][tx * 8 + 4]);
            float ra[8] = {a0.x, a0.y, a0.z, a0.w, a1.x, a1.y, a1.z, a1.w};
            float rb[8] = {w0.x, w0.y, w0.z, w0.w, w1.x, w1.y, w1.z, w1.w};
#pragma unroll
            for (int i = 0; i < 8; i++)
#pragma unroll
                for (int j = 0; j < 8; j++)
                    acc[i][j] += ra[i] * rb[j];
        }
    }

#pragma unroll
    for (int i = 0; i < 8; i++) {
        float4 o0 = make_float4(acc[i][0], acc[i][1], acc[i][2], acc[i][3]);
        float4 o1 = make_float4(acc[i][4], acc[i][5], acc[i][6], acc[i][7]);
        float* cp = C + (size_t)(m0 + ty * 8 + i) * N + n0 + tx * 8;
        *reinterpret_cast<float4*>(cp) = o0;
        *reinterpret_cast<float4*>(cp + 4) = o1;
    }
}

// ---------------------------------------------------------------------------
// Fused flash attention with structural bias.
// Block = (q-tile of 128 rows, head h, batch b). 128 threads (16 ty x 8 tx).
// Score phase: thread = 8 q-rows x 8 k-cols; PV phase: 8 q-rows x 8 d-cols.
// Both hot loops: 4 LDS.128 per 64 FFMA (balanced vs LDS bandwidth).
// Q transposed Qt[d][r], K transposed Kt[d][c], P transposed St[c][r],
// V natural Vs[c][d]. Structure bias folded into score init (pre-scaled).
// ---------------------------------------------------------------------------
__global__ __launch_bounds__(128, 2)
void attn_kernel(const float* __restrict__ Qh, const float* __restrict__ Kh,
                 const float* __restrict__ Vh, const float* __restrict__ structure,
                 float* __restrict__ ctx) {
    extern __shared__ float smf[];
    float* Qt = smf;                 // [64][132]  Qt[d][r], r in [0,128)
    float* St = Qt + 64 * 132;       // [64][132]  St[c][r]
    float* Kt = St + 64 * 132;       // [64][68]   Kt[d][c], c in [0,64)
    float* Vs = Kt + 64 * 68;        // [64][64]   Vs[c][d]

    const int tid = threadIdx.x;
    const int ty = tid >> 3;         // 0..15, 8 q-rows each
    const int tx = tid & 7;          // 0..7,  8 cols each
    const int q0 = blockIdx.x * 128;
    const int h = blockIdx.y;
    const int b = blockIdx.z;
    const size_t baseQ = ((size_t)b * SS + q0) * DD + h * 64;

    // Load Q tile [128 x 64] transposed into Qt[d][r]. 2048 float4, 16/thread.
#pragma unroll
    for (int t = 0; t < 16; t++) {
        int idx = t * 128 + tid;
        int r = idx >> 4, d4 = idx & 15;
        float4 qv = *reinterpret_cast<const float4*>(Qh + baseQ + (size_t)r * DD + d4 * 4);
        Qt[(d4 * 4 + 0) * 132 + r] = qv.x;
        Qt[(d4 * 4 + 1) * 132 + r] = qv.y;
        Qt[(d4 * 4 + 2) * 132 + r] = qv.z;
        Qt[(d4 * 4 + 3) * 132 + r] = qv.w;
    }

    float m_i[8], l_i[8], acc[8][8];
#pragma unroll
    for (int i = 0; i < 8; i++) {
        m_i[i] = -1e30f;
        l_i[i] = 0.0f;
#pragma unroll
        for (int j = 0; j < 8; j++) acc[i][j] = 0.0f;
    }
    const float scale = 0.125f;       // 1/sqrt(64)
    const float inv_scale = 8.0f;

    for (int kt = 0; kt < SS / 64; kt++) {
        const int k0 = kt * 64;
        const size_t baseK = ((size_t)b * SS + k0) * DD + h * 64;

        // Score init from structure bias (pre-divided by scale); LDG latency
        // hides under the K/V tile loads below.
        float s[8][8];
#pragma unroll
        for (int i = 0; i < 8; i++) {
            const float* sp = structure + ((size_t)b * SS + q0 + ty * 8 + i) * SS + k0 + tx * 8;
            const float4 sa = *reinterpret_cast<const float4*>(sp);
            const float4 sb = *reinterpret_cast<const float4*>(sp + 4);
            s[i][0] = sa.x * inv_scale; s[i][1] = sa.y * inv_scale;
            s[i][2] = sa.z * inv_scale; s[i][3] = sa.w * inv_scale;
            s[i][4] = sb.x * inv_scale; s[i][5] = sb.y * inv_scale;
            s[i][6] = sb.z * inv_scale; s[i][7] = sb.w * inv_scale;
        }

        __syncthreads();  // prior score/PV reads of Kt/Vs/St complete

        // V tile natural [c][d]: 1024 float4, 8/thread
#pragma unroll
        for (int t = 0; t < 8; t++) {
            int idx = t * 128 + tid;
            int c = idx >> 4, d4 = idx & 15;
            float4 vv = *reinterpret_cast<const float4*>(Vh + baseK + (size_t)c * DD + d4 * 4);
            *reinterpret_cast<float4*>(&Vs[c * 64 + d4 * 4]) = vv;
        }
        // K tile transposed into Kt[d][c]: 1024 float4, 8/thread
#pragma unroll
        for (int t = 0; t < 8; t++) {
            int idx = t * 128 + tid;
            int c = idx & 63, d4 = idx >> 6;
            float4 kv = *reinterpret_cast<const float4*>(Kh + baseK + (size_t)c * DD + d4 * 4);
            Kt[(d4 * 4 + 0) * 68 + c] = kv.x;
            Kt[(d4 * 4 + 1) * 68 + c] = kv.y;
            Kt[(d4 * 4 + 2) * 68 + c] = kv.z;
            Kt[(d4 * 4 + 3) * 68 + c] = kv.w;
        }
        __syncthreads();

        // Scores: s[i][j] += sum_d Q[r][d] * K[c][d]   (4 LDS.128 / 64 FFMA)
#pragma unroll 4
        for (int d = 0; d < 64; d++) {
            float4 qa = *reinterpret_cast<const float4*>(&Qt[d * 132 + ty * 8]);
            float4 qb = *reinterpret_cast<const float4*>(&Qt[d * 132 + ty * 8 + 4]);
            float4 ka = *reinterpret_cast<const float4*>(&Kt[d * 68 + tx * 8]);
            float4 kb = *reinterpret_cast<const float4*>(&Kt[d * 68 + tx * 8 + 4]);
            float rq[8] = {qa.x, qa.y, qa.z, qa.w, qb.x, qb.y, qb.z, qb.w};
            float rk[8] = {ka.x, ka.y, ka.z, ka.w, kb.x, kb.y, kb.z, kb.w};
#pragma unroll
            for (int i = 0; i < 8; i++)
#pragma unroll
                for (int j = 0; j < 8; j++)
                    s[i][j] += rq[i] * rk[j];
        }

        // Online softmax (per q-row; reduced across the 8 tx lanes)
#pragma unroll
        for (int i = 0; i < 8; i++) {
#pragma unroll
            for (int j = 0; j < 8; j++) s[i][j] *= scale;

            float tm = s[i][0];
#pragma unroll
            for (int j = 1; j < 8; j++) tm = fmaxf(tm, s[i][j]);
            tm = fmaxf(tm, __shfl_xor_sync(0xffffffffu, tm, 1));
            tm = fmaxf(tm, __shfl_xor_sync(0xffffffffu, tm, 2));
            tm = fmaxf(tm, __shfl_xor_sync(0xffffffffu, tm, 4));

            float mn = fmaxf(m_i[i], tm);
            float al = __expf(m_i[i] - mn);
            float rs = 0.0f;
#pragma unroll
            for (int j = 0; j < 8; j++) {
                s[i][j] = __expf(s[i][j] - mn);
                rs += s[i][j];
            }
            rs += __shfl_xor_sync(0xffffffffu, rs, 1);
            rs += __shfl_xor_sync(0xffffffffu, rs, 2);
            rs += __shfl_xor_sync(0xffffffffu, rs, 4);

            l_i[i] = l_i[i] * al + rs;
            m_i[i] = mn;
#pragma unroll
            for (int j = 0; j < 8; j++) acc[i][j] *= al;
        }

        // Store P transposed: St[c][r], c = tx*8+j
#pragma unroll
        for (int j = 0; j < 8; j++) {
            *reinterpret_cast<float4*>(&St[(tx * 8 + j) * 132 + ty * 8]) =
                make_float4(s[0][j], s[1][j], s[2][j], s[3][j]);
            *reinterpret_cast<float4*>(&St[(tx * 8 + j) * 132 + ty * 8 + 4]) =
                make_float4(s[4][j], s[5][j], s[6][j], s[7][j]);
        }
        __syncthreads();

        // PV: acc[i][j] += sum_c P[r][c] * V[c][d]   (4 LDS.128 / 64 FFMA)
#pragma unroll 4
        for (int c = 0; c < 64; c++) {
            float4 p0 = *reinterpret_cast<const float4*>(&St[c * 132 + ty * 8]);
            float4 p1 = *reinterpret_cast<const float4*>(&St[c * 132 + ty * 8 + 4]);
            float4 v0 = *reinterpret_cast<const float4*>(&Vs[c * 64 + tx * 8]);
            float4 v1 = *reinterpret_cast<const float4*>(&Vs[c * 64 + tx * 8 + 4]);
            float rp[8] = {p0.x, p0.y, p0.z, p0.w, p1.x, p1.y, p1.z, p1.w};
            float rv[8] = {v0.x, v0.y, v0.z, v0.w, v1.x, v1.y, v1.z, v1.w};
#pragma unroll
            for (int i = 0; i < 8; i++)
#pragma unroll
                for (int j = 0; j < 8; j++)
                    acc[i][j] += rp[i] * rv[j];
        }
    }

    // Epilogue: normalize and write ctx[b, q, h*64 + d]
#pragma unroll
    for (int i = 0; i < 8; i++) {
        float inv = 1.0f / l_i[i];
        float* cp = ctx + baseQ + (size_t)(ty * 8 + i) * DD + tx * 8;
        *reinterpret_cast<float4*>(cp) =
            make_float4(acc[i][0] * inv, acc[i][1] * inv, acc[i][2] * inv, acc[i][3] * inv);
        *reinterpret_cast<float4*>(cp + 4) =
            make_float4(acc[i][4] * inv, acc[i][5] * inv, acc[i][6] * inv, acc[i][7] * inv);
    }
}

// ---------------------------------------------------------------------------
// kernel_launch: 3 projection GEMMs -> fused attention -> output GEMM
// ---------------------------------------------------------------------------
extern "C" void kernel_launch(void* const* d_in, const int* in_sizes, int n_in,
                              void* d_out, int out_size) {
    const float* q   = (const float*)d_in[0];
    const float* k   = (const float*)d_in[1];
    const float* v   = (const float*)d_in[2];
    const float* str = (const float*)d_in[3];
    const float* Wq  = (const float*)d_in[4];
    const float* bq  = (const float*)d_in[5];
    const float* Wk  = (const float*)d_in[6];
    const float* bk  = (const float*)d_in[7];
    const float* Wv  = (const float*)d_in[8];
    const float* bv  = (const float*)d_in[9];
    const float* Wo  = (const float*)d_in[10];
    const float* bo  = (const float*)d_in[11];
    float* out = (float*)d_out;

    float *Qh, *Kh, *Vh, *Ctx;
    cudaGetSymbolAddress((void**)&Qh, g_Qh);
    cudaGetSymbolAddress((void**)&Kh, g_Kh);
    cudaGetSymbolAddress((void**)&Vh, g_Vh);
    cudaGetSymbolAddress((void**)&Ctx, g_ctx);

    const int M = BB * SS;   // 4096
    const int N = DD;        // 512
    const int K = DD;        // 512
    dim3 gemm_grid(M / 128, N / 128);   // 32 x 4 = 128 CTAs

    gemm_bias_kernel<<<gemm_grid, 256>>>(q, Wq, bq, Qh, M, N, K);
    gemm_bias_kernel<<<gemm_grid, 256>>>(k, Wk, bk, Kh, M, N, K);
    gemm_bias_kernel<<<gemm_grid, 256>>>(v, Wv, bv, Vh, M, N, K);

    const int att_smem = (64 * 132 * 2 + 64 * 68 + 64 * 64) * (int)sizeof(float);  // 101376
    cudaFuncSetAttribute(attn_kernel, cudaFuncAttributeMaxDynamicSharedMemorySize,
                         att_smem);
    dim3 att_grid(SS / 128, HH, BB);    // 16 x 8 x 2 = 256 CTAs
    attn_kernel<<<att_grid, 128, att_smem>>>(Qh, Kh, Vh, str, Ctx);

    gemm_bias_kernel<<<gemm_grid, 256>>>(Ctx, Wo, bo, out, M, N, K);
}

// round 5
// speedup vs baseline: 2.2794x; 2.2794x over previous
#include <cuda_runtime.h>
#include <cstdint>

#define BB 2
#define SS 2048
#define DD 512
#define HH 8

// Scratch (allocation-free: __device__ globals)
__device__ float g_Qh[BB * SS * DD];
__device__ float g_Kh[BB * SS * DD];
__device__ float g_Vh[BB * SS * DD];
__device__ float g_ctx[BB * SS * DD];

// ---------------------------------------------------------------------------
// Helpers
// ---------------------------------------------------------------------------
__device__ __forceinline__ float f2tf32(float x) {   // round-to-nearest tf32
    uint32_t r;
    asm("cvt.rna.tf32.f32 %0, %1;" : "=r"(r) : "f"(x));
    return __uint_as_float(r);
}
__device__ __forceinline__ float4 cvt4(float4 v) {
    return make_float4(f2tf32(v.x), f2tf32(v.y), f2tf32(v.z), f2tf32(v.w));
}
// m16n8k8 tf32 mma: D += A x B.  a[4], b[2] carry tf32 bit patterns.
__device__ __forceinline__ void mma_tf32(float* d, const uint32_t* a, const uint32_t* b) {
    asm volatile(
        "mma.sync.aligned.m16n8k8.row.col.f32.tf32.tf32.f32 "
        "{%0,%1,%2,%3}, {%4,%5,%6,%7}, {%8,%9}, {%0,%1,%2,%3};"
        : "+f"(d[0]), "+f"(d[1]), "+f"(d[2]), "+f"(d[3])
        : "r"(a[0]), "r"(a[1]), "r"(a[2]), "r"(a[3]), "r"(b[0]), "r"(b[1]));
}

// ===========================================================================
// GEMM: C[M,N] = A[M,K] @ W[K,N] + bias[N]   (tf32 mma.sync)
// 128x128 tile, 256 threads = 8 warps (4 m x 2 n), warp tile 32x64.
// smem tiles stored tf32-rounded. Register-staged prefetch of next K-slab.
// Strides: As row stride 20 (banks 20g+tg distinct), Ws stride 136 (8tg+g).
// ===========================================================================
__global__ __launch_bounds__(256)
void gemm_tc(const float* __restrict__ A, const float* __restrict__ W,
             const float* __restrict__ bias, float* __restrict__ C,
             int M, int N, int K) {
    __shared__ float As[128][20];    // As[m][k], k-extent 16
    __shared__ float Ws[16][136];    // Ws[k][n], n-extent 128

    const int tid = threadIdx.x;
    const int warp = tid >> 5;
    const int lane = tid & 31;
    const int g = lane >> 2;         // 0..7
    const int tg = lane & 3;         // 0..3
    const int wm = warp & 3;         // 0..3  (32 rows)
    const int wn = warp >> 2;        // 0..1  (64 cols)
    const int m0 = blockIdx.x * 128;
    const int n0 = blockIdx.y * 128;

    float acc[2][8][4];
#pragma unroll
    for (int mi = 0; mi < 2; mi++)
#pragma unroll
        for (int nj = 0; nj < 8; nj++)
#pragma unroll
            for (int c = 0; c < 4; c++) acc[mi][nj][c] = 0.0f;

    float4 pa[2], pw[2];
#pragma unroll
    for (int t = 0; t < 2; t++) {
        int idx = tid + t * 256;
        int r = idx >> 2, k4 = idx & 3;
        pa[t] = *reinterpret_cast<const float4*>(A + (size_t)(m0 + r) * K + k4 * 4);
        int kk = idx >> 5, n4 = idx & 31;
        pw[t] = *reinterpret_cast<const float4*>(W + (size_t)kk * N + n0 + n4 * 4);
    }

    const int nk = K / 16;
    for (int kc = 0; kc < nk; kc++) {
        __syncthreads();
#pragma unroll
        for (int t = 0; t < 2; t++) {
            int idx = tid + t * 256;
            int r = idx >> 2, k4 = idx & 3;
            *reinterpret_cast<float4*>(&As[r][k4 * 4]) = cvt4(pa[t]);
            int kk = idx >> 5, n4 = idx & 31;
            *reinterpret_cast<float4*>(&Ws[kk][n4 * 4]) = cvt4(pw[t]);
        }
        __syncthreads();

        if (kc + 1 < nk) {
#pragma unroll
            for (int t = 0; t < 2; t++) {
                int idx = tid + t * 256;
                int r = idx >> 2, k4 = idx & 3;
                pa[t] = *reinterpret_cast<const float4*>(
                    A + (size_t)(m0 + r) * K + (kc + 1) * 16 + k4 * 4);
                int kk = idx >> 5, n4 = idx & 31;
                pw[t] = *reinterpret_cast<const float4*>(
                    W + (size_t)((kc + 1) * 16 + kk) * N + n0 + n4 * 4);
            }
        }

#pragma unroll
        for (int ks = 0; ks < 2; ks++) {
            const int kb = ks * 8;
            uint32_t af[2][4];
#pragma unroll
            for (int mi = 0; mi < 2; mi++) {
                const int rb = wm * 32 + mi * 16;
                af[mi][0] = __float_as_uint(As[rb + g][kb + tg]);
                af[mi][1] = __float_as_uint(As[rb + g + 8][kb + tg]);
                af[mi][2] = __float_as_uint(As[rb + g][kb + tg + 4]);
                af[mi][3] = __float_as_uint(As[rb + g + 8][kb + tg + 4]);
            }
#pragma unroll
            for (int nj = 0; nj < 8; nj++) {
                const int col = wn * 64 + nj * 8 + g;
                uint32_t bf[2];
                bf[0] = __float_as_uint(Ws[kb + tg][col]);
                bf[1] = __float_as_uint(Ws[kb + tg + 4][col]);
                mma_tf32(acc[0][nj], af[0], bf);
                mma_tf32(acc[1][nj], af[1], bf);
            }
        }
    }

    // Epilogue: bias + STG.64 pairs
#pragma unroll
    for (int mi = 0; mi < 2; mi++) {
        const int rb = m0 + wm * 32 + mi * 16;
#pragma unroll
        for (int nj = 0; nj < 8; nj++) {
            const int colb = n0 + wn * 64 + nj * 8 + 2 * tg;
            const float2 bv = *reinterpret_cast<const float2*>(bias + colb);
            *reinterpret_cast<float2*>(C + (size_t)(rb + g) * N + colb) =
                make_float2(acc[mi][nj][0] + bv.x, acc[mi][nj][1] + bv.y);
            *reinterpret_cast<float2*>(C + (size_t)(rb + g + 8) * N + colb) =
                make_float2(acc[mi][nj][2] + bv.x, acc[mi][nj][3] + bv.y);
        }
    }
}

// ===========================================================================
// Fused flash attention (tf32 mma.sync) with structural bias.
// Block = (q-tile 128, head, batch). 256 threads = 8 warps; warp w owns
// q-rows 16w..16w+15. K-tile 64. Scores and output both via m16n8k8 mma;
// P round-trips through smem. Bias folded into score-accumulator init
// (pre-multiplied by 1/scale).
// smem strides: Qs/Ps 68 (banks 4g+tg), Ks 68, Vs 72 (banks 8tg+g).
// ===========================================================================
__global__ __launch_bounds__(256)
void attn_kernel(const float* __restrict__ Qh, const float* __restrict__ Kh,
                 const float* __restrict__ Vh, const float* __restrict__ structure,
                 float* __restrict__ ctx) {
    extern __shared__ float smf[];
    float* Qs = smf;                   // [128][68]
    float* Ks = Qs + 128 * 68;         // [64][68]
    float* Vs = Ks + 64 * 68;          // [64][72]
    float* Ps = Vs + 64 * 72;          // [128][68]

    const int tid = threadIdx.x;
    const int warp = tid >> 5;
    const int lane = tid & 31;
    const int g = lane >> 2;
    const int tg = lane & 3;
    const int q0 = blockIdx.x * 128;
    const int h = blockIdx.y;
    const int b = blockIdx.z;
    const int rq = warp * 16;          // warp's local q-row base
    const size_t baseQ = ((size_t)b * SS + q0) * DD + h * 64;

    // Load Q tile [128 x 64], tf32-rounded
#pragma unroll
    for (int t = 0; t < 8; t++) {
        int idx = tid + t * 256;
        int r = idx >> 4, d4 = idx & 15;
        float4 v = *reinterpret_cast<const float4*>(Qh + baseQ + (size_t)r * DD + d4 * 4);
        *reinterpret_cast<float4*>(&Qs[r * 68 + d4 * 4]) = cvt4(v);
    }

    float m_[2] = {-1e30f, -1e30f};
    float l_[2] = {0.0f, 0.0f};
    float oacc[8][4];
#pragma unroll
    for (int nj = 0; nj < 8; nj++)
#pragma unroll
        for (int c = 0; c < 4; c++) oacc[nj][c] = 0.0f;

    // Prefetch K/V tile 0 into registers
    float4 pk[4], pv[4];
    {
        const size_t baseK = ((size_t)b * SS) * DD + h * 64;
#pragma unroll
        for (int t = 0; t < 4; t++) {
            int idx = tid + t * 256;
            int c = idx >> 4, d4 = idx & 15;
            pk[t] = *reinterpret_cast<const float4*>(Kh + baseK + (size_t)c * DD + d4 * 4);
            pv[t] = *reinterpret_cast<const float4*>(Vh + baseK + (size_t)c * DD + d4 * 4);
        }
    }

    for (int kt = 0; kt < SS / 64; kt++) {
        const int k0g = kt * 64;
        __syncthreads();               // prior Ks/Vs/Ps reads complete
#pragma unroll
        for (int t = 0; t < 4; t++) {
            int idx = tid + t * 256;
            int c = idx >> 4, d4 = idx & 15;
            *reinterpret_cast<float4*>(&Ks[c * 68 + d4 * 4]) = cvt4(pk[t]);
            *reinterpret_cast<float4*>(&Vs[c * 72 + d4 * 4]) = cvt4(pv[t]);
        }
        __syncthreads();

        if (kt + 1 < SS / 64) {
            const size_t baseK = ((size_t)b * SS + (kt + 1) * 64) * DD + h * 64;
#pragma unroll
            for (int t = 0; t < 4; t++) {
                int idx = tid + t * 256;
                int c = idx >> 4, d4 = idx & 15;
                pk[t] = *reinterpret_cast<const float4*>(Kh + baseK + (size_t)c * DD + d4 * 4);
                pv[t] = *reinterpret_cast<const float4*>(Vh + baseK + (size_t)c * DD + d4 * 4);
            }
        }

        // Score accumulators init = structure-bias * (1/scale)
        float sacc[8][4];
#pragma unroll
        for (int nj = 0; nj < 8; nj++) {
            const int colb = k0g + nj * 8 + 2 * tg;
            const float2 s0 = *reinterpret_cast<const float2*>(
                structure + ((size_t)b * SS + q0 + rq + g) * SS + colb);
            const float2 s1 = *reinterpret_cast<const float2*>(
                structure + ((size_t)b * SS + q0 + rq + g + 8) * SS + colb);
            sacc[nj][0] = s0.x * 8.0f;
            sacc[nj][1] = s0.y * 8.0f;
            sacc[nj][2] = s1.x * 8.0f;
            sacc[nj][3] = s1.y * 8.0f;
        }

        // QK^T: A = Q rows [rq..rq+16), B[k=d][n=c] = Ks[c][d]
#pragma unroll
        for (int ks = 0; ks < 8; ks++) {
            const int kb = ks * 8;
            uint32_t af[4];
            af[0] = __float_as_uint(Qs[(rq + g) * 68 + kb + tg]);
            af[1] = __float_as_uint(Qs[(rq + g + 8) * 68 + kb + tg]);
            af[2] = __float_as_uint(Qs[(rq + g) * 68 + kb + tg + 4]);
            af[3] = __float_as_uint(Qs[(rq + g + 8) * 68 + kb + tg + 4]);
#pragma unroll
            for (int nj = 0; nj < 8; nj++) {
                uint32_t bf[2];
                bf[0] = __float_as_uint(Ks[(nj * 8 + g) * 68 + kb + tg]);
                bf[1] = __float_as_uint(Ks[(nj * 8 + g) * 68 + kb + tg + 4]);
                mma_tf32(sacc[nj], af, bf);
            }
        }

        // scale (bias was pre-multiplied by 1/scale so it lands exact)
#pragma unroll
        for (int nj = 0; nj < 8; nj++)
#pragma unroll
            for (int c = 0; c < 4; c++) sacc[nj][c] *= 0.125f;

        // Online softmax per row-half h2 (rows g and g+8); row stats are
        // spread over the 4 tg lanes -> shfl xor 1,2 reduces within quad.
#pragma unroll
        for (int h2 = 0; h2 < 2; h2++) {
            float mx = -1e30f;
#pragma unroll
            for (int nj = 0; nj < 8; nj++)
                mx = fmaxf(mx, fmaxf(sacc[nj][2 * h2], sacc[nj][2 * h2 + 1]));
            mx = fmaxf(mx, __shfl_xor_sync(0xffffffffu, mx, 1));
            mx = fmaxf(mx, __shfl_xor_sync(0xffffffffu, mx, 2));

            const float mn = fmaxf(m_[h2], mx);
            const float al = __expf(m_[h2] - mn);
            float rs = 0.0f;
#pragma unroll
            for (int nj = 0; nj < 8; nj++) {
                float p0 = __expf(sacc[nj][2 * h2] - mn);
                float p1 = __expf(sacc[nj][2 * h2 + 1] - mn);
                sacc[nj][2 * h2] = p0;
                sacc[nj][2 * h2 + 1] = p1;
                rs += p0 + p1;
            }
            rs += __shfl_xor_sync(0xffffffffu, rs, 1);
            rs += __shfl_xor_sync(0xffffffffu, rs, 2);

            l_[h2] = l_[h2] * al + rs;
            m_[h2] = mn;
#pragma unroll
            for (int nj = 0; nj < 8; nj++) {
                oacc[nj][2 * h2] *= al;
                oacc[nj][2 * h2 + 1] *= al;
            }
            // Store P row (tf32-rounded) into Ps
            const int prow = rq + g + 8 * h2;
#pragma unroll
            for (int nj = 0; nj < 8; nj++) {
                *reinterpret_cast<float2*>(&Ps[prow * 68 + nj * 8 + 2 * tg]) =
                    make_float2(f2tf32(sacc[nj][2 * h2]), f2tf32(sacc[nj][2 * h2 + 1]));
            }
        }
        __syncthreads();

        // PV: A = P rows [rq..rq+16) x k=c, B[k=c][n=d] = Vs[c][d]
#pragma unroll
        for (int ks = 0; ks < 8; ks++) {
            const int kb = ks * 8;
            uint32_t af[4];
            af[0] = __float_as_uint(Ps[(rq + g) * 68 + kb + tg]);
            af[1] = __float_as_uint(Ps[(rq + g + 8) * 68 + kb + tg]);
            af[2] = __float_as_uint(Ps[(rq + g) * 68 + kb + tg + 4]);
            af[3] = __float_as_uint(Ps[(rq + g + 8) * 68 + kb + tg + 4]);
#pragma unroll
            for (int nj = 0; nj < 8; nj++) {
                uint32_t bf[2];
                bf[0] = __float_as_uint(Vs[(kb + tg) * 72 + nj * 8 + g]);
                bf[1] = __float_as_uint(Vs[(kb + tg + 4) * 72 + nj * 8 + g]);
                mma_tf32(oacc[nj], af, bf);
            }
        }
    }

    // Epilogue: normalize, write ctx[b, q, h*64 + d]
    const float inv0 = 1.0f / l_[0];
    const float inv1 = 1.0f / l_[1];
#pragma unroll
    for (int nj = 0; nj < 8; nj++) {
        const int colb = nj * 8 + 2 * tg;
        float* cp0 = ctx + baseQ + (size_t)(rq + g) * DD + colb;
        float* cp1 = ctx + baseQ + (size_t)(rq + g + 8) * DD + colb;
        *reinterpret_cast<float2*>(cp0) =
            make_float2(oacc[nj][0] * inv0, oacc[nj][1] * inv0);
        *reinterpret_cast<float2*>(cp1) =
            make_float2(oacc[nj][2] * inv1, oacc[nj][3] * inv1);
    }
}

// ===========================================================================
// kernel_launch
// ===========================================================================
extern "C" void kernel_launch(void* const* d_in, const int* in_sizes, int n_in,
                              void* d_out, int out_size) {
    const float* q   = (const float*)d_in[0];
    const float* k   = (const float*)d_in[1];
    const float* v   = (const float*)d_in[2];
    const float* str = (const float*)d_in[3];
    const float* Wq  = (const float*)d_in[4];
    const float* bq  = (const float*)d_in[5];
    const float* Wk  = (const float*)d_in[6];
    const float* bk  = (const float*)d_in[7];
    const float* Wv  = (const float*)d_in[8];
    const float* bv  = (const float*)d_in[9];
    const float* Wo  = (const float*)d_in[10];
    const float* bo  = (const float*)d_in[11];
    float* out = (float*)d_out;

    float *Qh, *Kh, *Vh, *Ctx;
    cudaGetSymbolAddress((void**)&Qh, g_Qh);
    cudaGetSymbolAddress((void**)&Kh, g_Kh);
    cudaGetSymbolAddress((void**)&Vh, g_Vh);
    cudaGetSymbolAddress((void**)&Ctx, g_ctx);

    const int M = BB * SS;   // 4096
    const int N = DD;        // 512
    const int K = DD;        // 512
    dim3 gemm_grid(M / 128, N / 128);   // 32 x 4

    gemm_tc<<<gemm_grid, 256>>>(q, Wq, bq, Qh, M, N, K);
    gemm_tc<<<gemm_grid, 256>>>(k, Wk, bk, Kh, M, N, K);
    gemm_tc<<<gemm_grid, 256>>>(v, Wv, bv, Vh, M, N, K);

    const int att_smem = (128 * 68 + 64 * 68 + 64 * 72 + 128 * 68) * (int)sizeof(float);
    cudaFuncSetAttribute(attn_kernel, cudaFuncAttributeMaxDynamicSharedMemorySize,
                         att_smem);
    dim3 att_grid(SS / 128, HH, BB);    // 16 x 8 x 2 = 256 CTAs
    attn_kernel<<<att_grid, 256, att_smem>>>(Qh, Kh, Vh, str, Ctx);

    gemm_tc<<<gemm_grid, 256>>>(Ctx, Wo, bo, out, M, N, K);
}

// round 6
// speedup vs baseline: 2.4278x; 1.0651x over previous
#include <cuda_runtime.h>
#include <cstdint>

#define BB 2
#define SS 2048
#define DD 512
#define HH 8

// Scratch (allocation-free: __device__ globals)
__device__ float g_Qh[BB * SS * DD];
__device__ float g_Kh[BB * SS * DD];
__device__ float g_Vh[BB * SS * DD];
__device__ float g_ctx[BB * SS * DD];

// ---------------------------------------------------------------------------
// Helpers
// ---------------------------------------------------------------------------
__device__ __forceinline__ float f2tf32(float x) {   // round-to-nearest tf32
    uint32_t r;
    asm("cvt.rna.tf32.f32 %0, %1;" : "=r"(r) : "f"(x));
    return __uint_as_float(r);
}
__device__ __forceinline__ float4 cvt4(float4 v) {
    return make_float4(f2tf32(v.x), f2tf32(v.y), f2tf32(v.z), f2tf32(v.w));
}
__device__ __forceinline__ float4 cvt4s(float4 v, float s) {
    return make_float4(f2tf32(v.x * s), f2tf32(v.y * s), f2tf32(v.z * s), f2tf32(v.w * s));
}
// m16n8k8 tf32 mma: D += A x B.
__device__ __forceinline__ void mma_tf32(float* d, const uint32_t* a, const uint32_t* b) {
    asm volatile(
        "mma.sync.aligned.m16n8k8.row.col.f32.tf32.tf32.f32 "
        "{%0,%1,%2,%3}, {%4,%5,%6,%7}, {%8,%9}, {%0,%1,%2,%3};"
        : "+f"(d[0]), "+f"(d[1]), "+f"(d[2]), "+f"(d[3])
        : "r"(a[0]), "r"(a[1]), "r"(a[2]), "r"(a[3]), "r"(b[0]), "r"(b[1]));
}

// ===========================================================================
// GEMM body: C[M,N] = A[M,K] @ W[K,N] + bias[N]   (tf32 mma.sync)
// 128x128 tile, 256 threads = 8 warps (4 m x 2 n), warp tile 32x64.
// ===========================================================================
__device__ __forceinline__
void gemm_body(const float* __restrict__ A, const float* __restrict__ W,
               const float* __restrict__ bias, float* __restrict__ C,
               int M, int N, int K, int bx, int by) {
    __shared__ float As[128][20];    // As[m][k], k-extent 16
    __shared__ float Ws[16][136];    // Ws[k][n], n-extent 128

    const int tid = threadIdx.x;
    const int warp = tid >> 5;
    const int lane = tid & 31;
    const int g = lane >> 2;
    const int tg = lane & 3;
    const int wm = warp & 3;
    const int wn = warp >> 2;
    const int m0 = bx * 128;
    const int n0 = by * 128;

    float acc[2][8][4];
#pragma unroll
    for (int mi = 0; mi < 2; mi++)
#pragma unroll
        for (int nj = 0; nj < 8; nj++)
#pragma unroll
            for (int c = 0; c < 4; c++) acc[mi][nj][c] = 0.0f;

    float4 pa[2], pw[2];
#pragma unroll
    for (int t = 0; t < 2; t++) {
        int idx = tid + t * 256;
        int r = idx >> 2, k4 = idx & 3;
        pa[t] = *reinterpret_cast<const float4*>(A + (size_t)(m0 + r) * K + k4 * 4);
        int kk = idx >> 5, n4 = idx & 31;
        pw[t] = *reinterpret_cast<const float4*>(W + (size_t)kk * N + n0 + n4 * 4);
    }

    const int nk = K / 16;
    for (int kc = 0; kc < nk; kc++) {
        __syncthreads();
#pragma unroll
        for (int t = 0; t < 2; t++) {
            int idx = tid + t * 256;
            int r = idx >> 2, k4 = idx & 3;
            *reinterpret_cast<float4*>(&As[r][k4 * 4]) = cvt4(pa[t]);
            int kk = idx >> 5, n4 = idx & 31;
            *reinterpret_cast<float4*>(&Ws[kk][n4 * 4]) = cvt4(pw[t]);
        }
        __syncthreads();

        if (kc + 1 < nk) {
#pragma unroll
            for (int t = 0; t < 2; t++) {
                int idx = tid + t * 256;
                int r = idx >> 2, k4 = idx & 3;
                pa[t] = *reinterpret_cast<const float4*>(
                    A + (size_t)(m0 + r) * K + (kc + 1) * 16 + k4 * 4);
                int kk = idx >> 5, n4 = idx & 31;
                pw[t] = *reinterpret_cast<const float4*>(
                    W + (size_t)((kc + 1) * 16 + kk) * N + n0 + n4 * 4);
            }
        }

#pragma unroll
        for (int ks = 0; ks < 2; ks++) {
            const int kb = ks * 8;
            uint32_t af[2][4];
#pragma unroll
            for (int mi = 0; mi < 2; mi++) {
                const int rb = wm * 32 + mi * 16;
                af[mi][0] = __float_as_uint(As[rb + g][kb + tg]);
                af[mi][1] = __float_as_uint(As[rb + g + 8][kb + tg]);
                af[mi][2] = __float_as_uint(As[rb + g][kb + tg + 4]);
                af[mi][3] = __float_as_uint(As[rb + g + 8][kb + tg + 4]);
            }
#pragma unroll
            for (int nj = 0; nj < 8; nj++) {
                const int col = wn * 64 + nj * 8 + g;
                uint32_t bf[2];
                bf[0] = __float_as_uint(Ws[kb + tg][col]);
                bf[1] = __float_as_uint(Ws[kb + tg + 4][col]);
                mma_tf32(acc[0][nj], af[0], bf);
                mma_tf32(acc[1][nj], af[1], bf);
            }
        }
    }

#pragma unroll
    for (int mi = 0; mi < 2; mi++) {
        const int rb = m0 + wm * 32 + mi * 16;
#pragma unroll
        for (int nj = 0; nj < 8; nj++) {
            const int colb = n0 + wn * 64 + nj * 8 + 2 * tg;
            const float2 bv = *reinterpret_cast<const float2*>(bias + colb);
            *reinterpret_cast<float2*>(C + (size_t)(rb + g) * N + colb) =
                make_float2(acc[mi][nj][0] + bv.x, acc[mi][nj][1] + bv.y);
            *reinterpret_cast<float2*>(C + (size_t)(rb + g + 8) * N + colb) =
                make_float2(acc[mi][nj][2] + bv.x, acc[mi][nj][3] + bv.y);
        }
    }
}

// Fused Q/K/V projections: blockIdx.z selects the (A, W, bias, C) tuple.
__global__ __launch_bounds__(256)
void gemm3_tc(const float* A0, const float* A1, const float* A2,
              const float* W0, const float* W1, const float* W2,
              const float* b0, const float* b1, const float* b2,
              float* C0, float* C1, float* C2, int M, int N, int K) {
    const int z = blockIdx.z;
    const float* A = (z == 0) ? A0 : (z == 1) ? A1 : A2;
    const float* W = (z == 0) ? W0 : (z == 1) ? W1 : W2;
    const float* bi = (z == 0) ? b0 : (z == 1) ? b1 : b2;
    float* C = (z == 0) ? C0 : (z == 1) ? C1 : C2;
    gemm_body(A, W, bi, C, M, N, K, blockIdx.x, blockIdx.y);
}

__global__ __launch_bounds__(256)
void gemm_tc(const float* __restrict__ A, const float* __restrict__ W,
             const float* __restrict__ bias, float* __restrict__ C,
             int M, int N, int K) {
    gemm_body(A, W, bias, C, M, N, K, blockIdx.x, blockIdx.y);
}

// ===========================================================================
// Fused flash attention (tf32 mma.sync) with structural bias.
// Block = (q-tile 128, head, batch). 256 threads = 8 warps; warp w owns
// q-rows 16w..16w+15. K-tile 64. 2 CTAs/SM (regs<=128, smem 105.5KB).
// Q pre-scaled by 1/sqrt(dk) at load. P round-trip is warp-local (syncwarp).
// smem strides: Qs/Ps 68, Ks 68, Vs 72 (conflict-free for fragment feeds).
// ===========================================================================
__global__ __launch_bounds__(256, 2)
void attn_kernel(const float* __restrict__ Qh, const float* __restrict__ Kh,
                 const float* __restrict__ Vh, const float* __restrict__ structure,
                 float* __restrict__ ctx) {
    extern __shared__ float smf[];
    float* Qs = smf;                   // [128][68]
    float* Ks = Qs + 128 * 68;         // [64][68]
    float* Vs = Ks + 64 * 68;          // [64][72]
    float* Ps = Vs + 64 * 72;          // [128][68]

    const int tid = threadIdx.x;
    const int warp = tid >> 5;
    const int lane = tid & 31;
    const int g = lane >> 2;
    const int tg = lane & 3;
    const int q0 = blockIdx.x * 128;
    const int h = blockIdx.y;
    const int b = blockIdx.z;
    const int rq = warp * 16;
    const size_t baseQ = ((size_t)b * SS + q0) * DD + h * 64;

    // Load Q tile [128 x 64], pre-scaled by 1/8 then tf32-rounded
#pragma unroll
    for (int t = 0; t < 8; t++) {
        int idx = tid + t * 256;
        int r = idx >> 4, d4 = idx & 15;
        float4 v = *reinterpret_cast<const float4*>(Qh + baseQ + (size_t)r * DD + d4 * 4);
        *reinterpret_cast<float4*>(&Qs[r * 68 + d4 * 4]) = cvt4s(v, 0.125f);
    }

    float m_[2] = {-1e30f, -1e30f};
    float l_[2] = {0.0f, 0.0f};
    float oacc[8][4];
#pragma unroll
    for (int nj = 0; nj < 8; nj++)
#pragma unroll
        for (int c = 0; c < 4; c++) oacc[nj][c] = 0.0f;

    for (int kt = 0; kt < SS / 64; kt++) {
        const int k0g = kt * 64;
        const size_t baseK = ((size_t)b * SS + k0g) * DD + h * 64;

        // Score accumulators init = structure bias (Q carries the 1/8 scale);
        // LDG latency hides under the K/V load + barrier below.
        float sacc[8][4];
#pragma unroll
        for (int nj = 0; nj < 8; nj++) {
            const int colb = k0g + nj * 8 + 2 * tg;
            const float2 s0 = *reinterpret_cast<const float2*>(
                structure + ((size_t)b * SS + q0 + rq + g) * SS + colb);
            const float2 s1 = *reinterpret_cast<const float2*>(
                structure + ((size_t)b * SS + q0 + rq + g + 8) * SS + colb);
            sacc[nj][0] = s0.x;
            sacc[nj][1] = s0.y;
            sacc[nj][2] = s1.x;
            sacc[nj][3] = s1.y;
        }

        __syncthreads();               // all warps' prior-tile Ks/Vs reads done
#pragma unroll
        for (int t = 0; t < 4; t++) {
            int idx = tid + t * 256;
            int c = idx >> 4, d4 = idx & 15;
            float4 kv = *reinterpret_cast<const float4*>(Kh + baseK + (size_t)c * DD + d4 * 4);
            float4 vv = *reinterpret_cast<const float4*>(Vh + baseK + (size_t)c * DD + d4 * 4);
            *reinterpret_cast<float4*>(&Ks[c * 68 + d4 * 4]) = cvt4(kv);
            *reinterpret_cast<float4*>(&Vs[c * 72 + d4 * 4]) = cvt4(vv);
        }
        __syncthreads();

        // QK^T: A = Q rows [rq..rq+16), B[k=d][n=c] = Ks[c][d]
#pragma unroll
        for (int ks = 0; ks < 8; ks++) {
            const int kb = ks * 8;
            uint32_t af[4];
            af[0] = __float_as_uint(Qs[(rq + g) * 68 + kb + tg]);
            af[1] = __float_as_uint(Qs[(rq + g + 8) * 68 + kb + tg]);
            af[2] = __float_as_uint(Qs[(rq + g) * 68 + kb + tg + 4]);
            af[3] = __float_as_uint(Qs[(rq + g + 8) * 68 + kb + tg + 4]);
#pragma unroll
            for (int nj = 0; nj < 8; nj++) {
                uint32_t bf[2];
                bf[0] = __float_as_uint(Ks[(nj * 8 + g) * 68 + kb + tg]);
                bf[1] = __float_as_uint(Ks[(nj * 8 + g) * 68 + kb + tg + 4]);
                mma_tf32(sacc[nj], af, bf);
            }
        }

        // Online softmax per row-half (rows g, g+8); stats spread over 4 tg lanes.
#pragma unroll
        for (int h2 = 0; h2 < 2; h2++) {
            float mx = -1e30f;
#pragma unroll
            for (int nj = 0; nj < 8; nj++)
                mx = fmaxf(mx, fmaxf(sacc[nj][2 * h2], sacc[nj][2 * h2 + 1]));
            mx = fmaxf(mx, __shfl_xor_sync(0xffffffffu, mx, 1));
            mx = fmaxf(mx, __shfl_xor_sync(0xffffffffu, mx, 2));

            const float mn = fmaxf(m_[h2], mx);
            const float al = __expf(m_[h2] - mn);
            float rs = 0.0f;
#pragma unroll
            for (int nj = 0; nj < 8; nj++) {
                float p0 = __expf(sacc[nj][2 * h2] - mn);
                float p1 = __expf(sacc[nj][2 * h2 + 1] - mn);
                sacc[nj][2 * h2] = p0;
                sacc[nj][2 * h2 + 1] = p1;
                rs += p0 + p1;
            }
            rs += __shfl_xor_sync(0xffffffffu, rs, 1);
            rs += __shfl_xor_sync(0xffffffffu, rs, 2);

            l_[h2] = l_[h2] * al + rs;
            m_[h2] = mn;
#pragma unroll
            for (int nj = 0; nj < 8; nj++) {
                oacc[nj][2 * h2] *= al;
                oacc[nj][2 * h2 + 1] *= al;
            }
            const int prow = rq + g + 8 * h2;
#pragma unroll
            for (int nj = 0; nj < 8; nj++) {
                *reinterpret_cast<float2*>(&Ps[prow * 68 + nj * 8 + 2 * tg]) =
                    make_float2(f2tf32(sacc[nj][2 * h2]), f2tf32(sacc[nj][2 * h2 + 1]));
            }
        }
        __syncwarp();   // Ps rows are warp-local: cross-lane STS->LDS ordering only

        // PV: A = P rows [rq..rq+16) x k=c, B[k=c][n=d] = Vs[c][d]
#pragma unroll
        for (int ks = 0; ks < 8; ks++) {
            const int kb = ks * 8;
            uint32_t af[4];
            af[0] = __float_as_uint(Ps[(rq + g) * 68 + kb + tg]);
            af[1] = __float_as_uint(Ps[(rq + g + 8) * 68 + kb + tg]);
            af[2] = __float_as_uint(Ps[(rq + g) * 68 + kb + tg + 4]);
            af[3] = __float_as_uint(Ps[(rq + g + 8) * 68 + kb + tg + 4]);
#pragma unroll
            for (int nj = 0; nj < 8; nj++) {
                uint32_t bf[2];
                bf[0] = __float_as_uint(Vs[(kb + tg) * 72 + nj * 8 + g]);
                bf[1] = __float_as_uint(Vs[(kb + tg + 4) * 72 + nj * 8 + g]);
                mma_tf32(oacc[nj], af, bf);
            }
        }
    }

    // Epilogue: normalize, write ctx[b, q, h*64 + d]
    const float inv0 = 1.0f / l_[0];
    const float inv1 = 1.0f / l_[1];
#pragma unroll
    for (int nj = 0; nj < 8; nj++) {
        const int colb = nj * 8 + 2 * tg;
        float* cp0 = ctx + baseQ + (size_t)(rq + g) * DD + colb;
        float* cp1 = ctx + baseQ + (size_t)(rq + g + 8) * DD + colb;
        *reinterpret_cast<float2*>(cp0) =
            make_float2(oacc[nj][0] * inv0, oacc[nj][1] * inv0);
        *reinterpret_cast<float2*>(cp1) =
            make_float2(oacc[nj][2] * inv1, oacc[nj][3] * inv1);
    }
}

// ===========================================================================
// kernel_launch
// ===========================================================================
extern "C" void kernel_launch(void* const* d_in, const int* in_sizes, int n_in,
                              void* d_out, int out_size) {
    const float* q   = (const float*)d_in[0];
    const float* k   = (const float*)d_in[1];
    const float* v   = (const float*)d_in[2];
    const float* str = (const float*)d_in[3];
    const float* Wq  = (const float*)d_in[4];
    const float* bq  = (const float*)d_in[5];
    const float* Wk  = (const float*)d_in[6];
    const float* bk  = (const float*)d_in[7];
    const float* Wv  = (const float*)d_in[8];
    const float* bv  = (const float*)d_in[9];
    const float* Wo  = (const float*)d_in[10];
    const float* bo  = (const float*)d_in[11];
    float* out = (float*)d_out;

    float *Qh, *Kh, *Vh, *Ctx;
    cudaGetSymbolAddress((void**)&Qh, g_Qh);
    cudaGetSymbolAddress((void**)&Kh, g_Kh);
    cudaGetSymbolAddress((void**)&Vh, g_Vh);
    cudaGetSymbolAddress((void**)&Ctx, g_ctx);

    const int M = BB * SS;   // 4096
    const int N = DD;        // 512
    const int K = DD;        // 512

    dim3 g3(M / 128, N / 128, 3);       // fused Q/K/V projections: 384 CTAs
    gemm3_tc<<<g3, 256>>>(q, k, v, Wq, Wk, Wv, bq, bk, bv, Qh, Kh, Vh, M, N, K);

    const int att_smem = (128 * 68 + 64 * 68 + 64 * 72 + 128 * 68) * (int)sizeof(float);
    cudaFuncSetAttribute(attn_kernel, cudaFuncAttributeMaxDynamicSharedMemorySize,
                         att_smem);
    dim3 att_grid(SS / 128, HH, BB);    // 256 CTAs, 2 CTAs/SM -> 1 wave
    attn_kernel<<<att_grid, 256, att_smem>>>(Qh, Kh, Vh, str, Ctx);

    dim3 gemm_grid(M / 128, N / 128);
    gemm_tc<<<gemm_grid, 256>>>(Ctx, Wo, bo, out, M, N, K);
}

// round 7
// speedup vs baseline: 3.7869x; 1.5598x over previous
#include <cuda_runtime.h>
#include <cuda_fp16.h>
#include <cstdint>

#define BB 2
#define SS 2048
#define DD 512
#define HH 8

// Scratch (allocation-free: __device__ globals)
__device__ float g_Qh[BB * SS * DD];
__device__ float g_Kh[BB * SS * DD];
__device__ float g_Vh[BB * SS * DD];
__device__ float g_ctx[BB * SS * DD];

// ---------------------------------------------------------------------------
// Helpers
// ---------------------------------------------------------------------------
__device__ __forceinline__ float f2tf32(float x) {
    uint32_t r;
    asm("cvt.rna.tf32.f32 %0, %1;" : "=r"(r) : "f"(x));
    return __uint_as_float(r);
}
__device__ __forceinline__ float4 cvt4(float4 v) {
    return make_float4(f2tf32(v.x), f2tf32(v.y), f2tf32(v.z), f2tf32(v.w));
}
__device__ __forceinline__ void mma_tf32(float* d, const uint32_t* a, const uint32_t* b) {
    asm volatile(
        "mma.sync.aligned.m16n8k8.row.col.f32.tf32.tf32.f32 "
        "{%0,%1,%2,%3}, {%4,%5,%6,%7}, {%8,%9}, {%0,%1,%2,%3};"
        : "+f"(d[0]), "+f"(d[1]), "+f"(d[2]), "+f"(d[3])
        : "r"(a[0]), "r"(a[1]), "r"(a[2]), "r"(a[3]), "r"(b[0]), "r"(b[1]));
}
// fp16 m16n8k16 mma, fp32 accum
__device__ __forceinline__ void mma_f16(float* d, const uint32_t* a, const uint32_t* b) {
    asm volatile(
        "mma.sync.aligned.m16n8k16.row.col.f32.f16.f16.f32 "
        "{%0,%1,%2,%3}, {%4,%5,%6,%7}, {%8,%9}, {%0,%1,%2,%3};"
        : "+f"(d[0]), "+f"(d[1]), "+f"(d[2]), "+f"(d[3])
        : "r"(a[0]), "r"(a[1]), "r"(a[2]), "r"(a[3]), "r"(b[0]), "r"(b[1]));
}
__device__ __forceinline__ void ldsm_x4(uint32_t& r0, uint32_t& r1, uint32_t& r2,
                                        uint32_t& r3, uint32_t addr) {
    asm volatile("ldmatrix.sync.aligned.m8n8.x4.shared.b16 {%0,%1,%2,%3}, [%4];"
                 : "=r"(r0), "=r"(r1), "=r"(r2), "=r"(r3) : "r"(addr));
}
__device__ __forceinline__ void ldsm_x4_t(uint32_t& r0, uint32_t& r1, uint32_t& r2,
                                          uint32_t& r3, uint32_t addr) {
    asm volatile("ldmatrix.sync.aligned.m8n8.x4.trans.shared.b16 {%0,%1,%2,%3}, [%4];"
                 : "=r"(r0), "=r"(r1), "=r"(r2), "=r"(r3) : "r"(addr));
}
__device__ __forceinline__ uint32_t smem_u32(const void* p) {
    uint32_t a;
    asm("{ .reg .u64 t; cvta.to.shared.u64 t, %1; cvt.u32.u64 %0, t; }"
        : "=r"(a) : "l"(p));
    return a;
}
__device__ __forceinline__ uint32_t pack_h2(float a, float b) {
    __half2 h = __floats2half2_rn(a, b);
    return *reinterpret_cast<uint32_t*>(&h);
}

// ===========================================================================
// GEMM body: C[M,N] = A[M,K] @ W[K,N] + bias[N]   (tf32 mma.sync) — round-6
// ===========================================================================
__device__ __forceinline__
void gemm_body(const float* __restrict__ A, const float* __restrict__ W,
               const float* __restrict__ bias, float* __restrict__ C,
               int M, int N, int K, int bx, int by) {
    __shared__ float As[128][20];
    __shared__ float Ws[16][136];

    const int tid = threadIdx.x;
    const int warp = tid >> 5;
    const int lane = tid & 31;
    const int g = lane >> 2;
    const int tg = lane & 3;
    const int wm = warp & 3;
    const int wn = warp >> 2;
    const int m0 = bx * 128;
    const int n0 = by * 128;

    float acc[2][8][4];
#pragma unroll
    for (int mi = 0; mi < 2; mi++)
#pragma unroll
        for (int nj = 0; nj < 8; nj++)
#pragma unroll
            for (int c = 0; c < 4; c++) acc[mi][nj][c] = 0.0f;

    float4 pa[2], pw[2];
#pragma unroll
    for (int t = 0; t < 2; t++) {
        int idx = tid + t * 256;
        int r = idx >> 2, k4 = idx & 3;
        pa[t] = *reinterpret_cast<const float4*>(A + (size_t)(m0 + r) * K + k4 * 4);
        int kk = idx >> 5, n4 = idx & 31;
        pw[t] = *reinterpret_cast<const float4*>(W + (size_t)kk * N + n0 + n4 * 4);
    }

    const int nk = K / 16;
    for (int kc = 0; kc < nk; kc++) {
        __syncthreads();
#pragma unroll
        for (int t = 0; t < 2; t++) {
            int idx = tid + t * 256;
            int r = idx >> 2, k4 = idx & 3;
            *reinterpret_cast<float4*>(&As[r][k4 * 4]) = cvt4(pa[t]);
            int kk = idx >> 5, n4 = idx & 31;
            *reinterpret_cast<float4*>(&Ws[kk][n4 * 4]) = cvt4(pw[t]);
        }
        __syncthreads();

        if (kc + 1 < nk) {
#pragma unroll
            for (int t = 0; t < 2; t++) {
                int idx = tid + t * 256;
                int r = idx >> 2, k4 = idx & 3;
                pa[t] = *reinterpret_cast<const float4*>(
                    A + (size_t)(m0 + r) * K + (kc + 1) * 16 + k4 * 4);
                int kk = idx >> 5, n4 = idx & 31;
                pw[t] = *reinterpret_cast<const float4*>(
                    W + (size_t)((kc + 1) * 16 + kk) * N + n0 + n4 * 4);
            }
        }

#pragma unroll
        for (int ks = 0; ks < 2; ks++) {
            const int kb = ks * 8;
            uint32_t af[2][4];
#pragma unroll
            for (int mi = 0; mi < 2; mi++) {
                const int rb = wm * 32 + mi * 16;
                af[mi][0] = __float_as_uint(As[rb + g][kb + tg]);
                af[mi][1] = __float_as_uint(As[rb + g + 8][kb + tg]);
                af[mi][2] = __float_as_uint(As[rb + g][kb + tg + 4]);
                af[mi][3] = __float_as_uint(As[rb + g + 8][kb + tg + 4]);
            }
#pragma unroll
            for (int nj = 0; nj < 8; nj++) {
                const int col = wn * 64 + nj * 8 + g;
                uint32_t bf[2];
                bf[0] = __float_as_uint(Ws[kb + tg][col]);
                bf[1] = __float_as_uint(Ws[kb + tg + 4][col]);
                mma_tf32(acc[0][nj], af[0], bf);
                mma_tf32(acc[1][nj], af[1], bf);
            }
        }
    }

#pragma unroll
    for (int mi = 0; mi < 2; mi++) {
        const int rb = m0 + wm * 32 + mi * 16;
#pragma unroll
        for (int nj = 0; nj < 8; nj++) {
            const int colb = n0 + wn * 64 + nj * 8 + 2 * tg;
            const float2 bv = *reinterpret_cast<const float2*>(bias + colb);
            *reinterpret_cast<float2*>(C + (size_t)(rb + g) * N + colb) =
                make_float2(acc[mi][nj][0] + bv.x, acc[mi][nj][1] + bv.y);
            *reinterpret_cast<float2*>(C + (size_t)(rb + g + 8) * N + colb) =
                make_float2(acc[mi][nj][2] + bv.x, acc[mi][nj][3] + bv.y);
        }
    }
}

__global__ __launch_bounds__(256)
void gemm3_tc(const float* A0, const float* A1, const float* A2,
              const float* W0, const float* W1, const float* W2,
              const float* b0, const float* b1, const float* b2,
              float* C0, float* C1, float* C2, int M, int N, int K) {
    const int z = blockIdx.z;
    const float* A = (z == 0) ? A0 : (z == 1) ? A1 : A2;
    const float* W = (z == 0) ? W0 : (z == 1) ? W1 : W2;
    const float* bi = (z == 0) ? b0 : (z == 1) ? b1 : b2;
    float* C = (z == 0) ? C0 : (z == 1) ? C1 : C2;
    gemm_body(A, W, bi, C, M, N, K, blockIdx.x, blockIdx.y);
}

__global__ __launch_bounds__(256)
void gemm_tc(const float* __restrict__ A, const float* __restrict__ W,
             const float* __restrict__ bias, float* __restrict__ C,
             int M, int N, int K) {
    gemm_body(A, W, bias, C, M, N, K, blockIdx.x, blockIdx.y);
}

// ===========================================================================
// Fused flash attention — fp16 mma.sync m16n8k16 + ldmatrix.
// Block = (q-tile 128, head, batch). 256 threads = 8 warps; warp w: q-rows
// 16w..16w+15. K-tile 64. Q fragments preloaded to registers (Qs smem then
// reused as the P buffer; P rows are warp-local). smem rows padded to 72
// halfs (144B) so ldmatrix row-addresses land in distinct banks.
// Q pre-scaled by 1/sqrt(dk). Structure bias read fp32, added to fp32 sacc.
// ===========================================================================
__global__ __launch_bounds__(256, 2)
void attn_kernel(const float* __restrict__ Qh, const float* __restrict__ Kh,
                 const float* __restrict__ Vh, const float* __restrict__ structure,
                 float* __restrict__ ctx) {
    extern __shared__ char smc[];
    half* Qsh = reinterpret_cast<half*>(smc);   // [128][72] — reused as Ps
    half* Ksh = Qsh + 128 * 72;                 // [64][72]
    half* Vsh = Ksh + 64 * 72;                  // [64][72]
    const uint32_t qs_base = smem_u32(Qsh);
    const uint32_t ks_base = smem_u32(Ksh);
    const uint32_t vs_base = smem_u32(Vsh);

    const int tid = threadIdx.x;
    const int warp = tid >> 5;
    const int lane = tid & 31;
    const int g = lane >> 2;
    const int tg = lane & 3;
    const int q0 = blockIdx.x * 128;
    const int h = blockIdx.y;
    const int b = blockIdx.z;
    const int rq = warp * 16;
    const size_t baseQ = ((size_t)b * SS + q0) * DD + h * 64;

    // --- Load Q tile [128 x 64], scale by 1/8, to half smem ---
#pragma unroll
    for (int t = 0; t < 8; t++) {
        int idx = tid + t * 256;
        int r = idx >> 4, d4 = idx & 15;
        float4 v = *reinterpret_cast<const float4*>(Qh + baseQ + (size_t)r * DD + d4 * 4);
        uint32_t u01 = pack_h2(v.x * 0.125f, v.y * 0.125f);
        uint32_t u23 = pack_h2(v.z * 0.125f, v.w * 0.125f);
        *reinterpret_cast<uint2*>(&Qsh[r * 72 + d4 * 4]) = make_uint2(u01, u23);
    }
    __syncthreads();

    // --- Preload Q fragments: 4 k-slabs of 16 -> 16 regs ---
    uint32_t qf[4][4];
#pragma unroll
    for (int ks = 0; ks < 4; ks++) {
        const int row = rq + (lane & 15);
        const int col = ks * 16 + 8 * (lane >> 4);
        ldsm_x4(qf[ks][0], qf[ks][1], qf[ks][2], qf[ks][3],
                qs_base + (row * 72 + col) * 2);
    }

    float m_[2] = {-1e30f, -1e30f};
    float l_[2] = {0.0f, 0.0f};
    float oacc[8][4];
#pragma unroll
    for (int nj = 0; nj < 8; nj++)
#pragma unroll
        for (int c = 0; c < 4; c++) oacc[nj][c] = 0.0f;

    for (int kt = 0; kt < SS / 64; kt++) {
        const int k0g = kt * 64;
        const size_t baseK = ((size_t)b * SS + k0g) * DD + h * 64;

        // Score accumulators init = structure bias (fp32)
        float sacc[8][4];
#pragma unroll
        for (int nj = 0; nj < 8; nj++) {
            const int colb = k0g + nj * 8 + 2 * tg;
            const float2 s0 = *reinterpret_cast<const float2*>(
                structure + ((size_t)b * SS + q0 + rq + g) * SS + colb);
            const float2 s1 = *reinterpret_cast<const float2*>(
                structure + ((size_t)b * SS + q0 + rq + g + 8) * SS + colb);
            sacc[nj][0] = s0.x;
            sacc[nj][1] = s0.y;
            sacc[nj][2] = s1.x;
            sacc[nj][3] = s1.y;
        }

        __syncthreads();   // prior-tile Ks/Vs reads complete (and Q-frag ldsm, iter 0)
        // K,V tiles -> half smem
#pragma unroll
        for (int t = 0; t < 4; t++) {
            int idx = tid + t * 256;
            int c = idx >> 4, d4 = idx & 15;
            float4 kv = *reinterpret_cast<const float4*>(Kh + baseK + (size_t)c * DD + d4 * 4);
            float4 vv = *reinterpret_cast<const float4*>(Vh + baseK + (size_t)c * DD + d4 * 4);
            *reinterpret_cast<uint2*>(&Ksh[c * 72 + d4 * 4]) =
                make_uint2(pack_h2(kv.x, kv.y), pack_h2(kv.z, kv.w));
            *reinterpret_cast<uint2*>(&Vsh[c * 72 + d4 * 4]) =
                make_uint2(pack_h2(vv.x, vv.y), pack_h2(vv.z, vv.w));
        }
        __syncthreads();

        // --- QK^T: per k-slab of 16 (d), ldsm B non-trans from Ksh[n][k] ---
#pragma unroll
        for (int ks = 0; ks < 4; ks++) {
            const int kb = ks * 16;
#pragma unroll
            for (int nj2 = 0; nj2 < 4; nj2++) {
                const int row = nj2 * 16 + (lane & 7) + (((lane >> 4) & 1) * 8);
                const int col = kb + (((lane >> 3) & 1) * 8);
                uint32_t b0, b1, b2, b3;
                ldsm_x4(b0, b1, b2, b3, ks_base + (row * 72 + col) * 2);
                uint32_t bb0[2] = {b0, b1}, bb1[2] = {b2, b3};
                mma_f16(sacc[2 * nj2], qf[ks], bb0);
                mma_f16(sacc[2 * nj2 + 1], qf[ks], bb1);
            }
        }

        // --- Online softmax (rows g, g+8; stats spread over 4 tg lanes) ---
#pragma unroll
        for (int h2 = 0; h2 < 2; h2++) {
            float mx = -1e30f;
#pragma unroll
            for (int nj = 0; nj < 8; nj++)
                mx = fmaxf(mx, fmaxf(sacc[nj][2 * h2], sacc[nj][2 * h2 + 1]));
            mx = fmaxf(mx, __shfl_xor_sync(0xffffffffu, mx, 1));
            mx = fmaxf(mx, __shfl_xor_sync(0xffffffffu, mx, 2));

            const float mn = fmaxf(m_[h2], mx);
            const float al = __expf(m_[h2] - mn);
            float rs = 0.0f;
#pragma unroll
            for (int nj = 0; nj < 8; nj++) {
                float p0 = __expf(sacc[nj][2 * h2] - mn);
                float p1 = __expf(sacc[nj][2 * h2 + 1] - mn);
                sacc[nj][2 * h2] = p0;
                sacc[nj][2 * h2 + 1] = p1;
                rs += p0 + p1;
            }
            rs += __shfl_xor_sync(0xffffffffu, rs, 1);
            rs += __shfl_xor_sync(0xffffffffu, rs, 2);

            l_[h2] = l_[h2] * al + rs;
            m_[h2] = mn;
#pragma unroll
            for (int nj = 0; nj < 8; nj++) {
                oacc[nj][2 * h2] *= al;
                oacc[nj][2 * h2 + 1] *= al;
            }
            // Store P row as half2 into the (reused) Qsh buffer — warp-local rows
            const int prow = rq + g + 8 * h2;
#pragma unroll
            for (int nj = 0; nj < 8; nj++) {
                *reinterpret_cast<uint32_t*>(&Qsh[prow * 72 + nj * 8 + 2 * tg]) =
                    pack_h2(sacc[nj][2 * h2], sacc[nj][2 * h2 + 1]);
            }
        }
        __syncwarp();

        // --- PV: A = P (ldsm from Qsh rows rq..rq+15), B = V (ldsm trans) ---
#pragma unroll
        for (int ks = 0; ks < 4; ks++) {
            const int cb = ks * 16;
            uint32_t pf[4];
            {
                const int row = rq + (lane & 15);
                const int col = cb + 8 * (lane >> 4);
                ldsm_x4(pf[0], pf[1], pf[2], pf[3], qs_base + (row * 72 + col) * 2);
            }
#pragma unroll
            for (int db2 = 0; db2 < 4; db2++) {
                const int row = cb + (lane & 7) + (((lane >> 3) & 1) * 8);
                const int col = db2 * 16 + (((lane >> 4) & 1) * 8);
                uint32_t b0, b1, b2, b3;
                ldsm_x4_t(b0, b1, b2, b3, vs_base + (row * 72 + col) * 2);
                uint32_t bb0[2] = {b0, b1}, bb1[2] = {b2, b3};
                mma_f16(oacc[2 * db2], pf, bb0);
                mma_f16(oacc[2 * db2 + 1], pf, bb1);
            }
        }
    }

    // Epilogue: normalize, write ctx[b, q, h*64 + d]
    const float inv0 = 1.0f / l_[0];
    const float inv1 = 1.0f / l_[1];
#pragma unroll
    for (int nj = 0; nj < 8; nj++) {
        const int colb = nj * 8 + 2 * tg;
        float* cp0 = ctx + baseQ + (size_t)(rq + g) * DD + colb;
        float* cp1 = ctx + baseQ + (size_t)(rq + g + 8) * DD + colb;
        *reinterpret_cast<float2*>(cp0) =
            make_float2(oacc[nj][0] * inv0, oacc[nj][1] * inv0);
        *reinterpret_cast<float2*>(cp1) =
            make_float2(oacc[nj][2] * inv1, oacc[nj][3] * inv1);
    }
}

// ===========================================================================
// kernel_launch
// ===========================================================================
extern "C" void kernel_launch(void* const* d_in, const int* in_sizes, int n_in,
                              void* d_out, int out_size) {
    const float* q   = (const float*)d_in[0];
    const float* k   = (const float*)d_in[1];
    const float* v   = (const float*)d_in[2];
    const float* str = (const float*)d_in[3];
    const float* Wq  = (const float*)d_in[4];
    const float* bq  = (const float*)d_in[5];
    const float* Wk  = (const float*)d_in[6];
    const float* bk  = (const float*)d_in[7];
    const float* Wv  = (const float*)d_in[8];
    const float* bv  = (const float*)d_in[9];
    const float* Wo  = (const float*)d_in[10];
    const float* bo  = (const float*)d_in[11];
    float* out = (float*)d_out;

    float *Qh, *Kh, *Vh, *Ctx;
    cudaGetSymbolAddress((void**)&Qh, g_Qh);
    cudaGetSymbolAddress((void**)&Kh, g_Kh);
    cudaGetSymbolAddress((void**)&Vh, g_Vh);
    cudaGetSymbolAddress((void**)&Ctx, g_ctx);

    const int M = BB * SS;   // 4096
    const int N = DD;        // 512
    const int K = DD;        // 512

    dim3 g3(M / 128, N / 128, 3);
    gemm3_tc<<<g3, 256>>>(q, k, v, Wq, Wk, Wv, bq, bk, bv, Qh, Kh, Vh, M, N, K);

    const int att_smem = (128 + 64 + 64) * 72 * (int)sizeof(half);   // 36864 B
    cudaFuncSetAttribute(attn_kernel, cudaFuncAttributeMaxDynamicSharedMemorySize,
                         att_smem);
    dim3 att_grid(SS / 128, HH, BB);    // 256 CTAs, 2 CTAs/SM
    attn_kernel<<<att_grid, 256, att_smem>>>(Qh, Kh, Vh, str, Ctx);

    dim3 gemm_grid(M / 128, N / 128);
    gemm_tc<<<gemm_grid, 256>>>(Ctx, Wo, bo, out, M, N, K);
}

// round 8
// speedup vs baseline: 4.4354x; 1.1712x over previous
#include <cuda_runtime.h>
#include <cuda_fp16.h>
#include <cstdint>

#define BB 2
#define SS 2048
#define DD 512
#define HH 8

// Scratch (allocation-free: __device__ globals)
__device__ float g_Qh[BB * SS * DD];
__device__ float g_Kh[BB * SS * DD];
__device__ float g_Vh[BB * SS * DD];
__device__ float g_ctx[BB * SS * DD];

// ---------------------------------------------------------------------------
// Helpers
// ---------------------------------------------------------------------------
// fp16 m16n8k16 mma, fp32 accum
__device__ __forceinline__ void mma_f16(float* d, const uint32_t* a, const uint32_t* b) {
    asm volatile(
        "mma.sync.aligned.m16n8k16.row.col.f32.f16.f16.f32 "
        "{%0,%1,%2,%3}, {%4,%5,%6,%7}, {%8,%9}, {%0,%1,%2,%3};"
        : "+f"(d[0]), "+f"(d[1]), "+f"(d[2]), "+f"(d[3])
        : "r"(a[0]), "r"(a[1]), "r"(a[2]), "r"(a[3]), "r"(b[0]), "r"(b[1]));
}
__device__ __forceinline__ void ldsm_x4(uint32_t& r0, uint32_t& r1, uint32_t& r2,
                                        uint32_t& r3, uint32_t addr) {
    asm volatile("ldmatrix.sync.aligned.m8n8.x4.shared.b16 {%0,%1,%2,%3}, [%4];"
                 : "=r"(r0), "=r"(r1), "=r"(r2), "=r"(r3) : "r"(addr));
}
__device__ __forceinline__ void ldsm_x4_t(uint32_t& r0, uint32_t& r1, uint32_t& r2,
                                          uint32_t& r3, uint32_t addr) {
    asm volatile("ldmatrix.sync.aligned.m8n8.x4.trans.shared.b16 {%0,%1,%2,%3}, [%4];"
                 : "=r"(r0), "=r"(r1), "=r"(r2), "=r"(r3) : "r"(addr));
}
__device__ __forceinline__ uint32_t smem_u32(const void* p) {
    uint32_t a;
    asm("{ .reg .u64 t; cvta.to.shared.u64 t, %1; cvt.u32.u64 %0, t; }"
        : "=r"(a) : "l"(p));
    return a;
}
__device__ __forceinline__ uint32_t pack_h2(float a, float b) {
    __half2 h = __floats2half2_rn(a, b);
    return *reinterpret_cast<uint32_t*>(&h);
}

// ===========================================================================
// GEMM body (fp16 mma.sync + ldmatrix): C[M,N] = A[M,K] @ W[K,N] + bias[N]
// 128x128 tile, BK=32. 256 threads = 8 warps (4 m x 2 n), warp tile 32x64.
// Ah[128][40] halfs (bank stride 20, ldsm rows conflict-free);
// Ws[32][136] halfs (bank stride 4, ldsm rows conflict-free).
// Register-staged prefetch of next K-chunk.
// ===========================================================================
__device__ __forceinline__
void gemm_body(const float* __restrict__ A, const float* __restrict__ W,
               const float* __restrict__ bias, float* __restrict__ C,
               int M, int N, int K, int bx, int by) {
    __shared__ half Ah[128 * 40];
    __shared__ half Wsh[32 * 136];
    const uint32_t a_base = smem_u32(Ah);
    const uint32_t w_base = smem_u32(Wsh);

    const int tid = threadIdx.x;
    const int warp = tid >> 5;
    const int lane = tid & 31;
    const int g = lane >> 2;
    const int tg = lane & 3;
    const int wm = warp & 3;         // 0..3 -> 32 m-rows
    const int wn = warp >> 2;        // 0..1 -> 64 n-cols
    const int m0 = bx * 128;
    const int n0 = by * 128;

    float acc[2][8][4];
#pragma unroll
    for (int mi = 0; mi < 2; mi++)
#pragma unroll
        for (int nj = 0; nj < 8; nj++)
#pragma unroll
            for (int c = 0; c < 4; c++) acc[mi][nj][c] = 0.0f;

    // Preload chunk 0 into registers.
    // A: 128x32 floats = 1024 float4 (4/thread); W: 32x128 = 1024 float4.
    float4 pa[4], pw[4];
#pragma unroll
    for (int t = 0; t < 4; t++) {
        int idx = tid + t * 256;
        int rA = idx >> 3, k4 = idx & 7;
        pa[t] = *reinterpret_cast<const float4*>(A + (size_t)(m0 + rA) * K + k4 * 4);
        int kk = idx >> 5, n4 = idx & 31;
        pw[t] = *reinterpret_cast<const float4*>(W + (size_t)kk * N + n0 + n4 * 4);
    }

    const int nk = K / 32;
    for (int kc = 0; kc < nk; kc++) {
        __syncthreads();
#pragma unroll
        for (int t = 0; t < 4; t++) {
            int idx = tid + t * 256;
            int rA = idx >> 3, k4 = idx & 7;
            *reinterpret_cast<uint2*>(&Ah[rA * 40 + k4 * 4]) =
                make_uint2(pack_h2(pa[t].x, pa[t].y), pack_h2(pa[t].z, pa[t].w));
            int kk = idx >> 5, n4 = idx & 31;
            *reinterpret_cast<uint2*>(&Wsh[kk * 136 + n4 * 4]) =
                make_uint2(pack_h2(pw[t].x, pw[t].y), pack_h2(pw[t].z, pw[t].w));
        }
        __syncthreads();

        if (kc + 1 < nk) {
#pragma unroll
            for (int t = 0; t < 4; t++) {
                int idx = tid + t * 256;
                int rA = idx >> 3, k4 = idx & 7;
                pa[t] = *reinterpret_cast<const float4*>(
                    A + (size_t)(m0 + rA) * K + (kc + 1) * 32 + k4 * 4);
                int kk = idx >> 5, n4 = idx & 31;
                pw[t] = *reinterpret_cast<const float4*>(
                    W + (size_t)((kc + 1) * 32 + kk) * N + n0 + n4 * 4);
            }
        }

#pragma unroll
        for (int ks = 0; ks < 2; ks++) {
            const int kb = ks * 16;
            // A fragments: 2 m16 tiles (same pattern as verified attention Q)
            uint32_t af[2][4];
#pragma unroll
            for (int mi = 0; mi < 2; mi++) {
                const int row = wm * 32 + mi * 16 + (lane & 15);
                const int col = kb + 8 * (lane >> 4);
                ldsm_x4(af[mi][0], af[mi][1], af[mi][2], af[mi][3],
                        a_base + (row * 40 + col) * 2);
            }
            // B fragments: 4 n16 tiles via trans-ldsm (same pattern as attention V)
#pragma unroll
            for (int nj2 = 0; nj2 < 4; nj2++) {
                const int row = kb + (lane & 7) + (((lane >> 3) & 1) * 8);
                const int col = wn * 64 + nj2 * 16 + (((lane >> 4) & 1) * 8);
                uint32_t b0, b1, b2, b3;
                ldsm_x4_t(b0, b1, b2, b3, w_base + (row * 136 + col) * 2);
                uint32_t bb0[2] = {b0, b1}, bb1[2] = {b2, b3};
                mma_f16(acc[0][2 * nj2], af[0], bb0);
                mma_f16(acc[0][2 * nj2 + 1], af[0], bb1);
                mma_f16(acc[1][2 * nj2], af[1], bb0);
                mma_f16(acc[1][2 * nj2 + 1], af[1], bb1);
            }
        }
    }

#pragma unroll
    for (int mi = 0; mi < 2; mi++) {
        const int rb = m0 + wm * 32 + mi * 16;
#pragma unroll
        for (int nj = 0; nj < 8; nj++) {
            const int colb = n0 + wn * 64 + nj * 8 + 2 * tg;
            const float2 bv = *reinterpret_cast<const float2*>(bias + colb);
            *reinterpret_cast<float2*>(C + (size_t)(rb + g) * N + colb) =
                make_float2(acc[mi][nj][0] + bv.x, acc[mi][nj][1] + bv.y);
            *reinterpret_cast<float2*>(C + (size_t)(rb + g + 8) * N + colb) =
                make_float2(acc[mi][nj][2] + bv.x, acc[mi][nj][3] + bv.y);
        }
    }
}

__global__ __launch_bounds__(256)
void gemm3_tc(const float* A0, const float* A1, const float* A2,
              const float* W0, const float* W1, const float* W2,
              const float* b0, const float* b1, const float* b2,
              float* C0, float* C1, float* C2, int M, int N, int K) {
    const int z = blockIdx.z;
    const float* A = (z == 0) ? A0 : (z == 1) ? A1 : A2;
    const float* W = (z == 0) ? W0 : (z == 1) ? W1 : W2;
    const float* bi = (z == 0) ? b0 : (z == 1) ? b1 : b2;
    float* C = (z == 0) ? C0 : (z == 1) ? C1 : C2;
    gemm_body(A, W, bi, C, M, N, K, blockIdx.x, blockIdx.y);
}

__global__ __launch_bounds__(256)
void gemm_tc(const float* __restrict__ A, const float* __restrict__ W,
             const float* __restrict__ bias, float* __restrict__ C,
             int M, int N, int K) {
    gemm_body(A, W, bias, C, M, N, K, blockIdx.x, blockIdx.y);
}

// ===========================================================================
// Fused flash attention — fp16 mma.sync m16n8k16 + ldmatrix (round-7, WIN).
// ===========================================================================
__global__ __launch_bounds__(256, 2)
void attn_kernel(const float* __restrict__ Qh, const float* __restrict__ Kh,
                 const float* __restrict__ Vh, const float* __restrict__ structure,
                 float* __restrict__ ctx) {
    extern __shared__ char smc[];
    half* Qsh = reinterpret_cast<half*>(smc);   // [128][72] — reused as Ps
    half* Ksh = Qsh + 128 * 72;                 // [64][72]
    half* Vsh = Ksh + 64 * 72;                  // [64][72]
    const uint32_t qs_base = smem_u32(Qsh);
    const uint32_t ks_base = smem_u32(Ksh);
    const uint32_t vs_base = smem_u32(Vsh);

    const int tid = threadIdx.x;
    const int warp = tid >> 5;
    const int lane = tid & 31;
    const int g = lane >> 2;
    const int tg = lane & 3;
    const int q0 = blockIdx.x * 128;
    const int h = blockIdx.y;
    const int b = blockIdx.z;
    const int rq = warp * 16;
    const size_t baseQ = ((size_t)b * SS + q0) * DD + h * 64;

    // --- Load Q tile [128 x 64], scale by 1/8, to half smem ---
#pragma unroll
    for (int t = 0; t < 8; t++) {
        int idx = tid + t * 256;
        int r = idx >> 4, d4 = idx & 15;
        float4 v = *reinterpret_cast<const float4*>(Qh + baseQ + (size_t)r * DD + d4 * 4);
        uint32_t u01 = pack_h2(v.x * 0.125f, v.y * 0.125f);
        uint32_t u23 = pack_h2(v.z * 0.125f, v.w * 0.125f);
        *reinterpret_cast<uint2*>(&Qsh[r * 72 + d4 * 4]) = make_uint2(u01, u23);
    }
    __syncthreads();

    // --- Preload Q fragments: 4 k-slabs of 16 -> 16 regs ---
    uint32_t qf[4][4];
#pragma unroll
    for (int ks = 0; ks < 4; ks++) {
        const int row = rq + (lane & 15);
        const int col = ks * 16 + 8 * (lane >> 4);
        ldsm_x4(qf[ks][0], qf[ks][1], qf[ks][2], qf[ks][3],
                qs_base + (row * 72 + col) * 2);
    }

    float m_[2] = {-1e30f, -1e30f};
    float l_[2] = {0.0f, 0.0f};
    float oacc[8][4];
#pragma unroll
    for (int nj = 0; nj < 8; nj++)
#pragma unroll
        for (int c = 0; c < 4; c++) oacc[nj][c] = 0.0f;

    for (int kt = 0; kt < SS / 64; kt++) {
        const int k0g = kt * 64;
        const size_t baseK = ((size_t)b * SS + k0g) * DD + h * 64;

        // Score accumulators init = structure bias (fp32)
        float sacc[8][4];
#pragma unroll
        for (int nj = 0; nj < 8; nj++) {
            const int colb = k0g + nj * 8 + 2 * tg;
            const float2 s0 = *reinterpret_cast<const float2*>(
                structure + ((size_t)b * SS + q0 + rq + g) * SS + colb);
            const float2 s1 = *reinterpret_cast<const float2*>(
                structure + ((size_t)b * SS + q0 + rq + g + 8) * SS + colb);
            sacc[nj][0] = s0.x;
            sacc[nj][1] = s0.y;
            sacc[nj][2] = s1.x;
            sacc[nj][3] = s1.y;
        }

        __syncthreads();   // prior-tile Ks/Vs reads complete (and Q-frag ldsm, iter 0)
#pragma unroll
        for (int t = 0; t < 4; t++) {
            int idx = tid + t * 256;
            int c = idx >> 4, d4 = idx & 15;
            float4 kv = *reinterpret_cast<const float4*>(Kh + baseK + (size_t)c * DD + d4 * 4);
            float4 vv = *reinterpret_cast<const float4*>(Vh + baseK + (size_t)c * DD + d4 * 4);
            *reinterpret_cast<uint2*>(&Ksh[c * 72 + d4 * 4]) =
                make_uint2(pack_h2(kv.x, kv.y), pack_h2(kv.z, kv.w));
            *reinterpret_cast<uint2*>(&Vsh[c * 72 + d4 * 4]) =
                make_uint2(pack_h2(vv.x, vv.y), pack_h2(vv.z, vv.w));
        }
        __syncthreads();

        // --- QK^T ---
#pragma unroll
        for (int ks = 0; ks < 4; ks++) {
            const int kb = ks * 16;
#pragma unroll
            for (int nj2 = 0; nj2 < 4; nj2++) {
                const int row = nj2 * 16 + (lane & 7) + (((lane >> 4) & 1) * 8);
                const int col = kb + (((lane >> 3) & 1) * 8);
                uint32_t b0, b1, b2, b3;
                ldsm_x4(b0, b1, b2, b3, ks_base + (row * 72 + col) * 2);
                uint32_t bb0[2] = {b0, b1}, bb1[2] = {b2, b3};
                mma_f16(sacc[2 * nj2], qf[ks], bb0);
                mma_f16(sacc[2 * nj2 + 1], qf[ks], bb1);
            }
        }

        // --- Online softmax ---
#pragma unroll
        for (int h2 = 0; h2 < 2; h2++) {
            float mx = -1e30f;
#pragma unroll
            for (int nj = 0; nj < 8; nj++)
                mx = fmaxf(mx, fmaxf(sacc[nj][2 * h2], sacc[nj][2 * h2 + 1]));
            mx = fmaxf(mx, __shfl_xor_sync(0xffffffffu, mx, 1));
            mx = fmaxf(mx, __shfl_xor_sync(0xffffffffu, mx, 2));

            const float mn = fmaxf(m_[h2], mx);
            const float al = __expf(m_[h2] - mn);
            float rs = 0.0f;
#pragma unroll
            for (int nj = 0; nj < 8; nj++) {
                float p0 = __expf(sacc[nj][2 * h2] - mn);
                float p1 = __expf(sacc[nj][2 * h2 + 1] - mn);
                sacc[nj][2 * h2] = p0;
                sacc[nj][2 * h2 + 1] = p1;
                rs += p0 + p1;
            }
            rs += __shfl_xor_sync(0xffffffffu, rs, 1);
            rs += __shfl_xor_sync(0xffffffffu, rs, 2);

            l_[h2] = l_[h2] * al + rs;
            m_[h2] = mn;
#pragma unroll
            for (int nj = 0; nj < 8; nj++) {
                oacc[nj][2 * h2] *= al;
                oacc[nj][2 * h2 + 1] *= al;
            }
            const int prow = rq + g + 8 * h2;
#pragma unroll
            for (int nj = 0; nj < 8; nj++) {
                *reinterpret_cast<uint32_t*>(&Qsh[prow * 72 + nj * 8 + 2 * tg]) =
                    pack_h2(sacc[nj][2 * h2], sacc[nj][2 * h2 + 1]);
            }
        }
        __syncwarp();

        // --- PV ---
#pragma unroll
        for (int ks = 0; ks < 4; ks++) {
            const int cb = ks * 16;
            uint32_t pf[4];
            {
                const int row = rq + (lane & 15);
                const int col = cb + 8 * (lane >> 4);
                ldsm_x4(pf[0], pf[1], pf[2], pf[3], qs_base + (row * 72 + col) * 2);
            }
#pragma unroll
            for (int db2 = 0; db2 < 4; db2++) {
                const int row = cb + (lane & 7) + (((lane >> 3) & 1) * 8);
                const int col = db2 * 16 + (((lane >> 4) & 1) * 8);
                uint32_t b0, b1, b2, b3;
                ldsm_x4_t(b0, b1, b2, b3, vs_base + (row * 72 + col) * 2);
                uint32_t bb0[2] = {b0, b1}, bb1[2] = {b2, b3};
                mma_f16(oacc[2 * db2], pf, bb0);
                mma_f16(oacc[2 * db2 + 1], pf, bb1);
            }
        }
    }

    // Epilogue: normalize, write ctx[b, q, h*64 + d]
    const float inv0 = 1.0f / l_[0];
    const float inv1 = 1.0f / l_[1];
#pragma unroll
    for (int nj = 0; nj < 8; nj++) {
        const int colb = nj * 8 + 2 * tg;
        float* cp0 = ctx + baseQ + (size_t)(rq + g) * DD + colb;
        float* cp1 = ctx + baseQ + (size_t)(rq + g + 8) * DD + colb;
        *reinterpret_cast<float2*>(cp0) =
            make_float2(oacc[nj][0] * inv0, oacc[nj][1] * inv0);
        *reinterpret_cast<float2*>(cp1) =
            make_float2(oacc[nj][2] * inv1, oacc[nj][3] * inv1);
    }
}

// ===========================================================================
// kernel_launch
// ===========================================================================
extern "C" void kernel_launch(void* const* d_in, const int* in_sizes, int n_in,
                              void* d_out, int out_size) {
    const float* q   = (const float*)d_in[0];
    const float* k   = (const float*)d_in[1];
    const float* v   = (const float*)d_in[2];
    const float* str = (const float*)d_in[3];
    const float* Wq  = (const float*)d_in[4];
    const float* bq  = (const float*)d_in[5];
    const float* Wk  = (const float*)d_in[6];
    const float* bk  = (const float*)d_in[7];
    const float* Wv  = (const float*)d_in[8];
    const float* bv  = (const float*)d_in[9];
    const float* Wo  = (const float*)d_in[10];
    const float* bo  = (const float*)d_in[11];
    float* out = (float*)d_out;

    float *Qh, *Kh, *Vh, *Ctx;
    cudaGetSymbolAddress((void**)&Qh, g_Qh);
    cudaGetSymbolAddress((void**)&Kh, g_Kh);
    cudaGetSymbolAddress((void**)&Vh, g_Vh);
    cudaGetSymbolAddress((void**)&Ctx, g_ctx);

    const int M = BB * SS;   // 4096
    const int N = DD;        // 512
    const int K = DD;        // 512

    dim3 g3(M / 128, N / 128, 3);
    gemm3_tc<<<g3, 256>>>(q, k, v, Wq, Wk, Wv, bq, bk, bv, Qh, Kh, Vh, M, N, K);

    const int att_smem = (128 + 64 + 64) * 72 * (int)sizeof(half);   // 36864 B
    cudaFuncSetAttribute(attn_kernel, cudaFuncAttributeMaxDynamicSharedMemorySize,
                         att_smem);
    dim3 att_grid(SS / 128, HH, BB);    // 256 CTAs, 2 CTAs/SM
    attn_kernel<<<att_grid, 256, att_smem>>>(Qh, Kh, Vh, str, Ctx);

    dim3 gemm_grid(M / 128, N / 128);
    gemm_tc<<<gemm_grid, 256>>>(Ctx, Wo, bo, out, M, N, K);
}

// round 9
// speedup vs baseline: 5.0603x; 1.1409x over previous
#include <cuda_runtime.h>
#include <cuda_fp16.h>
#include <cstdint>

#define BB 2
#define SS 2048
#define DD 512
#define HH 8

// Scratch (allocation-free: __device__ globals)
__device__ half  g_qin[BB * SS * DD];
__device__ half  g_kin[BB * SS * DD];
__device__ half  g_vin[BB * SS * DD];
__device__ half  g_Wqh[DD * DD];
__device__ half  g_Wkh[DD * DD];
__device__ half  g_Wvh[DD * DD];
__device__ half  g_Qh[BB * SS * DD];
__device__ half  g_Kh[BB * SS * DD];
__device__ half  g_Vh[BB * SS * DD];
__device__ float g_ctx[BB * SS * DD];

// ---------------------------------------------------------------------------
// Helpers
// ---------------------------------------------------------------------------
__device__ __forceinline__ void mma_f16(float* d, const uint32_t* a, const uint32_t* b) {
    asm volatile(
        "mma.sync.aligned.m16n8k16.row.col.f32.f16.f16.f32 "
        "{%0,%1,%2,%3}, {%4,%5,%6,%7}, {%8,%9}, {%0,%1,%2,%3};"
        : "+f"(d[0]), "+f"(d[1]), "+f"(d[2]), "+f"(d[3])
        : "r"(a[0]), "r"(a[1]), "r"(a[2]), "r"(a[3]), "r"(b[0]), "r"(b[1]));
}
// tf32 kept for the fp32 out-GEMM path helpers (unused) — removed.
__device__ __forceinline__ void ldsm_x4(uint32_t& r0, uint32_t& r1, uint32_t& r2,
                                        uint32_t& r3, uint32_t addr) {
    asm volatile("ldmatrix.sync.aligned.m8n8.x4.shared.b16 {%0,%1,%2,%3}, [%4];"
                 : "=r"(r0), "=r"(r1), "=r"(r2), "=r"(r3) : "r"(addr));
}
__device__ __forceinline__ void ldsm_x4_t(uint32_t& r0, uint32_t& r1, uint32_t& r2,
                                          uint32_t& r3, uint32_t addr) {
    asm volatile("ldmatrix.sync.aligned.m8n8.x4.trans.shared.b16 {%0,%1,%2,%3}, [%4];"
                 : "=r"(r0), "=r"(r1), "=r"(r2), "=r"(r3) : "r"(addr));
}
__device__ __forceinline__ uint32_t smem_u32(const void* p) {
    uint32_t a;
    asm("{ .reg .u64 t; cvta.to.shared.u64 t, %1; cvt.u32.u64 %0, t; }"
        : "=r"(a) : "l"(p));
    return a;
}
__device__ __forceinline__ uint32_t pack_h2(float a, float b) {
    __half2 h = __floats2half2_rn(a, b);
    return *reinterpret_cast<uint32_t*>(&h);
}
__device__ __forceinline__ void cp16(uint32_t dst, const void* src) {
    asm volatile("cp.async.cg.shared.global [%0], [%1], 16;" :: "r"(dst), "l"(src));
}
__device__ __forceinline__ void cp_commit() {
    asm volatile("cp.async.commit_group;" ::: "memory");
}
template <int N>
__device__ __forceinline__ void cp_wait() {
    asm volatile("cp.async.wait_group %0;" :: "n"(N) : "memory");
}

// ===========================================================================
// Convert kernel: fp32 -> fp16 for q,k,v inputs and Wq,Wk,Wv
// ===========================================================================
__global__ __launch_bounds__(256)
void convert_kernel(const float4* q, const float4* k, const float4* v,
                    const float4* wq, const float4* wk, const float4* wv,
                    uint2* qh, uint2* kh, uint2* vh,
                    uint2* wqh, uint2* wkh, uint2* wvh) {
    const int NI = BB * SS * DD / 4;   // 524288
    const int NW = DD * DD / 4;        // 65536
    int i = blockIdx.x * 256 + threadIdx.x;
    const float4* src; uint2* dst; int off;
    if (i < NI)               { src = q;  dst = qh;  off = i; }
    else if (i < 2 * NI)      { src = k;  dst = kh;  off = i - NI; }
    else if (i < 3 * NI)      { src = v;  dst = vh;  off = i - 2 * NI; }
    else if (i < 3 * NI + NW) { src = wq; dst = wqh; off = i - 3 * NI; }
    else if (i < 3 * NI + 2 * NW) { src = wk; dst = wkh; off = i - 3 * NI - NW; }
    else                      { src = wv; dst = wvh; off = i - 3 * NI - 2 * NW; }
    float4 x = src[off];
    dst[off] = make_uint2(pack_h2(x.x, x.y), pack_h2(x.z, x.w));
}

// ===========================================================================
// gemm3_h: C_half[M,N] = (A_half[M,K] @ W_half[K,N] + bias_f32) * scale
// 128x128 tile, BK=32, 4-stage cp.async pipeline (ahead-2), 1 barrier/chunk.
// Stage (halfs): A[128][40] (5120) + W[32][136] (4352) = 9472.
// z==0 (Q) gets scale = 1/8 folded into the epilogue.
// ===========================================================================
__global__ __launch_bounds__(256, 2)
void gemm3_h(const half* A0, const half* A1, const half* A2,
             const half* W0, const half* W1, const half* W2,
             const float* b0, const float* b1, const float* b2,
             half* C0, half* C1, half* C2, int M, int N, int K) {
    extern __shared__ half smh[];
    const uint32_t sm_base = smem_u32(smh);

    const int z = blockIdx.z;
    const half* A = (z == 0) ? A0 : (z == 1) ? A1 : A2;
    const half* W = (z == 0) ? W0 : (z == 1) ? W1 : W2;
    const float* bias = (z == 0) ? b0 : (z == 1) ? b1 : b2;
    half* C = (z == 0) ? C0 : (z == 1) ? C1 : C2;
    const float scale = (z == 0) ? 0.125f : 1.0f;

    const int tid = threadIdx.x;
    const int warp = tid >> 5;
    const int lane = tid & 31;
    const int g = lane >> 2;
    const int tg = lane & 3;
    const int wm = warp & 3;
    const int wn = warp >> 2;
    const int m0 = blockIdx.x * 128;
    const int n0 = blockIdx.y * 128;

    auto issue_stage = [&](int kc, int s) {
        const uint32_t sa = sm_base + (uint32_t)(s * 9472) * 2;
        const uint32_t sw = sa + 5120 * 2;
#pragma unroll
        for (int t = 0; t < 2; t++) {
            int idx = tid + t * 256;
            int row = idx >> 2, c4 = idx & 3;
            cp16(sa + (uint32_t)(row * 40 + c4 * 8) * 2,
                 A + (size_t)(m0 + row) * K + kc * 32 + c4 * 8);
        }
#pragma unroll
        for (int t = 0; t < 2; t++) {
            int idx = tid + t * 256;
            int row = idx >> 4, c16 = idx & 15;
            cp16(sw + (uint32_t)(row * 136 + c16 * 8) * 2,
                 W + (size_t)(kc * 32 + row) * N + n0 + c16 * 8);
        }
        cp_commit();
    };

    float acc[2][8][4];
#pragma unroll
    for (int mi = 0; mi < 2; mi++)
#pragma unroll
        for (int nj = 0; nj < 8; nj++)
#pragma unroll
            for (int c = 0; c < 4; c++) acc[mi][nj][c] = 0.0f;

    issue_stage(0, 0);
    issue_stage(1, 1);

    const int nk = K / 32;   // 16
    for (int kc = 0; kc < nk; kc++) {
        const int s = kc & 3;
        if (kc + 2 < nk) { issue_stage(kc + 2, (kc + 2) & 3); cp_wait<2>(); }
        else if (kc + 1 < nk) { cp_wait<1>(); }
        else { cp_wait<0>(); }
        __syncthreads();

        const uint32_t a_base = sm_base + (uint32_t)(s * 9472) * 2;
        const uint32_t w_base = a_base + 5120 * 2;
#pragma unroll
        for (int ks = 0; ks < 2; ks++) {
            const int kb = ks * 16;
            uint32_t af[2][4];
#pragma unroll
            for (int mi = 0; mi < 2; mi++) {
                const int row = wm * 32 + mi * 16 + (lane & 15);
                const int col = kb + 8 * (lane >> 4);
                ldsm_x4(af[mi][0], af[mi][1], af[mi][2], af[mi][3],
                        a_base + (uint32_t)(row * 40 + col) * 2);
            }
#pragma unroll
            for (int nj2 = 0; nj2 < 4; nj2++) {
                const int row = kb + (lane & 7) + (((lane >> 3) & 1) * 8);
                const int col = wn * 64 + nj2 * 16 + (((lane >> 4) & 1) * 8);
                uint32_t b0r, b1r, b2r, b3r;
                ldsm_x4_t(b0r, b1r, b2r, b3r, w_base + (uint32_t)(row * 136 + col) * 2);
                uint32_t bb0[2] = {b0r, b1r}, bb1[2] = {b2r, b3r};
                mma_f16(acc[0][2 * nj2], af[0], bb0);
                mma_f16(acc[0][2 * nj2 + 1], af[0], bb1);
                mma_f16(acc[1][2 * nj2], af[1], bb0);
                mma_f16(acc[1][2 * nj2 + 1], af[1], bb1);
            }
        }
    }

    // Epilogue: (acc + bias) * scale -> half
#pragma unroll
    for (int mi = 0; mi < 2; mi++) {
        const int rb = m0 + wm * 32 + mi * 16;
#pragma unroll
        for (int nj = 0; nj < 8; nj++) {
            const int colb = n0 + wn * 64 + nj * 8 + 2 * tg;
            const float2 bv = *reinterpret_cast<const float2*>(bias + colb);
            *reinterpret_cast<uint32_t*>(C + (size_t)(rb + g) * N + colb) =
                pack_h2((acc[mi][nj][0] + bv.x) * scale, (acc[mi][nj][1] + bv.y) * scale);
            *reinterpret_cast<uint32_t*>(C + (size_t)(rb + g + 8) * N + colb) =
                pack_h2((acc[mi][nj][2] + bv.x) * scale, (acc[mi][nj][3] + bv.y) * scale);
        }
    }
}

// ===========================================================================
// Fused flash attention — fp16 mma + ldmatrix + cp.async K/V ring (3 stages).
// Qh/Kh/Vh are half in gmem; Q pre-scaled by 1/8. Single barrier per k-tile.
// smem (halfs): Qsh[128][72] (reused as P) + 3 x (K[64][72] + V[64][72]).
// ===========================================================================
__global__ __launch_bounds__(256, 2)
void attn_kernel(const half* __restrict__ Qg, const half* __restrict__ Kg,
                 const half* __restrict__ Vg, const float* __restrict__ structure,
                 float* __restrict__ ctx) {
    extern __shared__ half smh[];
    const uint32_t qs_base = smem_u32(smh);

    const int tid = threadIdx.x;
    const int warp = tid >> 5;
    const int lane = tid & 31;
    const int g = lane >> 2;
    const int tg = lane & 3;
    const int q0 = blockIdx.x * 128;
    const int h = blockIdx.y;
    const int b = blockIdx.z;
    const int rq = warp * 16;
    const size_t baseQ = ((size_t)b * SS + q0) * DD + h * 64;

    auto issue_kv = [&](int kt, int s) {
        const size_t baseK = ((size_t)b * SS + kt * 64) * DD + h * 64;
        const uint32_t kb = qs_base + (uint32_t)(9216 + s * 9216) * 2;
        const uint32_t vb = kb + 4608 * 2;
#pragma unroll
        for (int t = 0; t < 2; t++) {
            int idx = tid + t * 256;
            int row = idx >> 3, c8 = idx & 7;
            cp16(kb + (uint32_t)(row * 72 + c8 * 8) * 2,
                 Kg + baseK + (size_t)row * DD + c8 * 8);
        }
#pragma unroll
        for (int t = 0; t < 2; t++) {
            int idx = tid + t * 256;
            int row = idx >> 3, c8 = idx & 7;
            cp16(vb + (uint32_t)(row * 72 + c8 * 8) * 2,
                 Vg + baseK + (size_t)row * DD + c8 * 8);
        }
        cp_commit();
    };

    // K/V tile 0 first (overlaps Q wait), then Q tile.
    issue_kv(0, 0);
#pragma unroll
    for (int t = 0; t < 4; t++) {
        int idx = tid + t * 256;
        int row = idx >> 3, c8 = idx & 7;
        cp16(qs_base + (uint32_t)(row * 72 + c8 * 8) * 2,
             Qg + baseQ + (size_t)row * DD + c8 * 8);
    }
    cp_commit();
    cp_wait<0>();
    __syncthreads();

    // Preload Q fragments (Qsh then becomes the P buffer)
    uint32_t qf[4][4];
#pragma unroll
    for (int ks = 0; ks < 4; ks++) {
        const int row = rq + (lane & 15);
        const int col = ks * 16 + 8 * (lane >> 4);
        ldsm_x4(qf[ks][0], qf[ks][1], qf[ks][2], qf[ks][3],
                qs_base + (uint32_t)(row * 72 + col) * 2);
    }

    float m_[2] = {-1e30f, -1e30f};
    float l_[2] = {0.0f, 0.0f};
    float oacc[8][4];
#pragma unroll
    for (int nj = 0; nj < 8; nj++)
#pragma unroll
        for (int c = 0; c < 4; c++) oacc[nj][c] = 0.0f;

    for (int kt = 0; kt < SS / 64; kt++) {
        const int s = kt % 3;
        const int k0g = kt * 64;

        // Structure bias -> score accumulators (LDG latency hides under
        // the issue/wait/barrier and the leading ldsm batch)
        float sacc[8][4];
#pragma unroll
        for (int nj = 0; nj < 8; nj++) {
            const int colb = k0g + nj * 8 + 2 * tg;
            const float2 s0 = *reinterpret_cast<const float2*>(
                structure + ((size_t)b * SS + q0 + rq + g) * SS + colb);
            const float2 s1 = *reinterpret_cast<const float2*>(
                structure + ((size_t)b * SS + q0 + rq + g + 8) * SS + colb);
            sacc[nj][0] = s0.x;
            sacc[nj][1] = s0.y;
            sacc[nj][2] = s1.x;
            sacc[nj][3] = s1.y;
        }

        if (kt + 1 < SS / 64) { issue_kv(kt + 1, (kt + 1) % 3); cp_wait<1>(); }
        else { cp_wait<0>(); }
        __syncthreads();

        const uint32_t ks_base = qs_base + (uint32_t)(9216 + s * 9216) * 2;
        const uint32_t vs_base = ks_base + 4608 * 2;

        // --- QK^T ---
#pragma unroll
        for (int ks = 0; ks < 4; ks++) {
            const int kb = ks * 16;
#pragma unroll
            for (int nj2 = 0; nj2 < 4; nj2++) {
                const int row = nj2 * 16 + (lane & 7) + (((lane >> 4) & 1) * 8);
                const int col = kb + (((lane >> 3) & 1) * 8);
                uint32_t b0r, b1r, b2r, b3r;
                ldsm_x4(b0r, b1r, b2r, b3r, ks_base + (uint32_t)(row * 72 + col) * 2);
                uint32_t bb0[2] = {b0r, b1r}, bb1[2] = {b2r, b3r};
                mma_f16(sacc[2 * nj2], qf[ks], bb0);
                mma_f16(sacc[2 * nj2 + 1], qf[ks], bb1);
            }
        }

        // --- Online softmax ---
#pragma unroll
        for (int h2 = 0; h2 < 2; h2++) {
            float mx = -1e30f;
#pragma unroll
            for (int nj = 0; nj < 8; nj++)
                mx = fmaxf(mx, fmaxf(sacc[nj][2 * h2], sacc[nj][2 * h2 + 1]));
            mx = fmaxf(mx, __shfl_xor_sync(0xffffffffu, mx, 1));
            mx = fmaxf(mx, __shfl_xor_sync(0xffffffffu, mx, 2));

            const float mn = fmaxf(m_[h2], mx);
            const float al = __expf(m_[h2] - mn);
            float rs = 0.0f;
#pragma unroll
            for (int nj = 0; nj < 8; nj++) {
                float p0 = __expf(sacc[nj][2 * h2] - mn);
                float p1 = __expf(sacc[nj][2 * h2 + 1] - mn);
                sacc[nj][2 * h2] = p0;
                sacc[nj][2 * h2 + 1] = p1;
                rs += p0 + p1;
            }
            rs += __shfl_xor_sync(0xffffffffu, rs, 1);
            rs += __shfl_xor_sync(0xffffffffu, rs, 2);

            l_[h2] = l_[h2] * al + rs;
            m_[h2] = mn;
#pragma unroll
            for (int nj = 0; nj < 8; nj++) {
                oacc[nj][2 * h2] *= al;
                oacc[nj][2 * h2 + 1] *= al;
            }
            const int prow = rq + g + 8 * h2;
#pragma unroll
            for (int nj = 0; nj < 8; nj++) {
                *reinterpret_cast<uint32_t*>(&smh[prow * 72 + nj * 8 + 2 * tg]) =
                    pack_h2(sacc[nj][2 * h2], sacc[nj][2 * h2 + 1]);
            }
        }
        __syncwarp();   // P rows are warp-local

        // --- PV ---
#pragma unroll
        for (int ks = 0; ks < 4; ks++) {
            const int cb = ks * 16;
            uint32_t pf[4];
            {
                const int row = rq + (lane & 15);
                const int col = cb + 8 * (lane >> 4);
                ldsm_x4(pf[0], pf[1], pf[2], pf[3],
                        qs_base + (uint32_t)(row * 72 + col) * 2);
            }
#pragma unroll
            for (int db2 = 0; db2 < 4; db2++) {
                const int row = cb + (lane & 7) + (((lane >> 3) & 1) * 8);
                const int col = db2 * 16 + (((lane >> 4) & 1) * 8);
                uint32_t b0r, b1r, b2r, b3r;
                ldsm_x4_t(b0r, b1r, b2r, b3r, vs_base + (uint32_t)(row * 72 + col) * 2);
                uint32_t bb0[2] = {b0r, b1r}, bb1[2] = {b2r, b3r};
                mma_f16(oacc[2 * db2], pf, bb0);
                mma_f16(oacc[2 * db2 + 1], pf, bb1);
            }
        }
    }

    // Epilogue: normalize, write ctx (fp32)
    const float inv0 = 1.0f / l_[0];
    const float inv1 = 1.0f / l_[1];
#pragma unroll
    for (int nj = 0; nj < 8; nj++) {
        const int colb = nj * 8 + 2 * tg;
        float* cp0 = ctx + baseQ + (size_t)(rq + g) * DD + colb;
        float* cp1 = ctx + baseQ + (size_t)(rq + g + 8) * DD + colb;
        *reinterpret_cast<float2*>(cp0) =
            make_float2(oacc[nj][0] * inv0, oacc[nj][1] * inv0);
        *reinterpret_cast<float2*>(cp1) =
            make_float2(oacc[nj][2] * inv1, oacc[nj][3] * inv1);
    }
}

// ===========================================================================
// Out-GEMM (round-8 fp32-input fp16-mma body, unchanged)
// ===========================================================================
__global__ __launch_bounds__(256)
void gemm_tc(const float* __restrict__ A, const float* __restrict__ W,
             const float* __restrict__ bias, float* __restrict__ C,
             int M, int N, int K) {
    __shared__ half Ah[128 * 40];
    __shared__ half Wsh[32 * 136];
    const uint32_t a_base = smem_u32(Ah);
    const uint32_t w_base = smem_u32(Wsh);

    const int tid = threadIdx.x;
    const int warp = tid >> 5;
    const int lane = tid & 31;
    const int g = lane >> 2;
    const int tg = lane & 3;
    const int wm = warp & 3;
    const int wn = warp >> 2;
    const int m0 = blockIdx.x * 128;
    const int n0 = blockIdx.y * 128;

    float acc[2][8][4];
#pragma unroll
    for (int mi = 0; mi < 2; mi++)
#pragma unroll
        for (int nj = 0; nj < 8; nj++)
#pragma unroll
            for (int c = 0; c < 4; c++) acc[mi][nj][c] = 0.0f;

    float4 pa[4], pw[4];
#pragma unroll
    for (int t = 0; t < 4; t++) {
        int idx = tid + t * 256;
        int rA = idx >> 3, k4 = idx & 7;
        pa[t] = *reinterpret_cast<const float4*>(A + (size_t)(m0 + rA) * K + k4 * 4);
        int kk = idx >> 5, n4 = idx & 31;
        pw[t] = *reinterpret_cast<const float4*>(W + (size_t)kk * N + n0 + n4 * 4);
    }

    const int nk = K / 32;
    for (int kc = 0; kc < nk; kc++) {
        __syncthreads();
#pragma unroll
        for (int t = 0; t < 4; t++) {
            int idx = tid + t * 256;
            int rA = idx >> 3, k4 = idx & 7;
            *reinterpret_cast<uint2*>(&Ah[rA * 40 + k4 * 4]) =
                make_uint2(pack_h2(pa[t].x, pa[t].y), pack_h2(pa[t].z, pa[t].w));
            int kk = idx >> 5, n4 = idx & 31;
            *reinterpret_cast<uint2*>(&Wsh[kk * 136 + n4 * 4]) =
                make_uint2(pack_h2(pw[t].x, pw[t].y), pack_h2(pw[t].z, pw[t].w));
        }
        __syncthreads();

        if (kc + 1 < nk) {
#pragma unroll
            for (int t = 0; t < 4; t++) {
                int idx = tid + t * 256;
                int rA = idx >> 3, k4 = idx & 7;
                pa[t] = *reinterpret_cast<const float4*>(
                    A + (size_t)(m0 + rA) * K + (kc + 1) * 32 + k4 * 4);
                int kk = idx >> 5, n4 = idx & 31;
                pw[t] = *reinterpret_cast<const float4*>(
                    W + (size_t)((kc + 1) * 32 + kk) * N + n0 + n4 * 4);
            }
        }

#pragma unroll
        for (int ks = 0; ks < 2; ks++) {
            const int kb = ks * 16;
            uint32_t af[2][4];
#pragma unroll
            for (int mi = 0; mi < 2; mi++) {
                const int row = wm * 32 + mi * 16 + (lane & 15);
                const int col = kb + 8 * (lane >> 4);
                ldsm_x4(af[mi][0], af[mi][1], af[mi][2], af[mi][3],
                        a_base + (row * 40 + col) * 2);
            }
#pragma unroll
            for (int nj2 = 0; nj2 < 4; nj2++) {
                const int row = kb + (lane & 7) + (((lane >> 3) & 1) * 8);
                const int col = wn * 64 + nj2 * 16 + (((lane >> 4) & 1) * 8);
                uint32_t b0r, b1r, b2r, b3r;
                ldsm_x4_t(b0r, b1r, b2r, b3r, w_base + (row * 136 + col) * 2);
                uint32_t bb0[2] = {b0r, b1r}, bb1[2] = {b2r, b3r};
                mma_f16(acc[0][2 * nj2], af[0], bb0);
                mma_f16(acc[0][2 * nj2 + 1], af[0], bb1);
                mma_f16(acc[1][2 * nj2], af[1], bb0);
                mma_f16(acc[1][2 * nj2 + 1], af[1], bb1);
            }
        }
    }

#pragma unroll
    for (int mi = 0; mi < 2; mi++) {
        const int rb = m0 + wm * 32 + mi * 16;
#pragma unroll
        for (int nj = 0; nj < 8; nj++) {
            const int colb = n0 + wn * 64 + nj * 8 + 2 * tg;
            const float2 bv = *reinterpret_cast<const float2*>(bias + colb);
            *reinterpret_cast<float2*>(C + (size_t)(rb + g) * N + colb) =
                make_float2(acc[mi][nj][0] + bv.x, acc[mi][nj][1] + bv.y);
            *reinterpret_cast<float2*>(C + (size_t)(rb + g + 8) * N + colb) =
                make_float2(acc[mi][nj][2] + bv.x, acc[mi][nj][3] + bv.y);
        }
    }
}

// ===========================================================================
// kernel_launch
// ===========================================================================
extern "C" void kernel_launch(void* const* d_in, const int* in_sizes, int n_in,
                              void* d_out, int out_size) {
    const float* q   = (const float*)d_in[0];
    const float* k   = (const float*)d_in[1];
    const float* v   = (const float*)d_in[2];
    const float* str = (const float*)d_in[3];
    const float* bq  = (const float*)d_in[5];
    const float* bk  = (const float*)d_in[7];
    const float* bv  = (const float*)d_in[9];
    const float* Wo  = (const float*)d_in[10];
    const float* bo  = (const float*)d_in[11];
    const float* Wq  = (const float*)d_in[4];
    const float* Wk  = (const float*)d_in[6];
    const float* Wv  = (const float*)d_in[8];
    float* out = (float*)d_out;

    half *qin, *kin, *vin, *Wqh, *Wkh, *Wvh, *Qh, *Kh, *Vh;
    float *Ctx;
    cudaGetSymbolAddress((void**)&qin, g_qin);
    cudaGetSymbolAddress((void**)&kin, g_kin);
    cudaGetSymbolAddress((void**)&vin, g_vin);
    cudaGetSymbolAddress((void**)&Wqh, g_Wqh);
    cudaGetSymbolAddress((void**)&Wkh, g_Wkh);
    cudaGetSymbolAddress((void**)&Wvh, g_Wvh);
    cudaGetSymbolAddress((void**)&Qh, g_Qh);
    cudaGetSymbolAddress((void**)&Kh, g_Kh);
    cudaGetSymbolAddress((void**)&Vh, g_Vh);
    cudaGetSymbolAddress((void**)&Ctx, g_ctx);

    const int M = BB * SS;   // 4096
    const int N = DD;        // 512
    const int K = DD;        // 512

    // 1) convert inputs + weights to fp16
    const int NI = BB * SS * DD / 4, NW = DD * DD / 4;
    convert_kernel<<<(3 * NI + 3 * NW) / 256, 256>>>(
        (const float4*)q, (const float4*)k, (const float4*)v,
        (const float4*)Wq, (const float4*)Wk, (const float4*)Wv,
        (uint2*)qin, (uint2*)kin, (uint2*)vin,
        (uint2*)Wqh, (uint2*)Wkh, (uint2*)Wvh);

    // 2) fused Q/K/V projections (cp.async pipeline), outputs half
    const int g3_smem = 4 * 9472 * (int)sizeof(half);   // 75776 B
    cudaFuncSetAttribute(gemm3_h, cudaFuncAttributeMaxDynamicSharedMemorySize, g3_smem);
    dim3 g3(M / 128, N / 128, 3);
    gemm3_h<<<g3, 256, g3_smem>>>(qin, kin, vin, Wqh, Wkh, Wvh,
                                  bq, bk, bv, Qh, Kh, Vh, M, N, K);

    // 3) attention
    const int att_smem = (9216 + 3 * 9216) * (int)sizeof(half);   // 73728 B
    cudaFuncSetAttribute(attn_kernel, cudaFuncAttributeMaxDynamicSharedMemorySize,
                         att_smem);
    dim3 att_grid(SS / 128, HH, BB);
    attn_kernel<<<att_grid, 256, att_smem>>>(Qh, Kh, Vh, str, Ctx);

    // 4) output projection (fp32 ctx)
    dim3 gemm_grid(M / 128, N / 128);
    gemm_tc<<<gemm_grid, 256>>>(Ctx, Wo, bo, out, M, N, K);
}

// round 11
// speedup vs baseline: 5.4398x; 1.0750x over previous
#include <cuda_runtime.h>
#include <cuda_fp16.h>
#include <cstdint>

#define BB 2
#define SS 2048
#define DD 512
#define HH 8

// Scratch (allocation-free: __device__ globals)
__device__ half  g_qin[BB * SS * DD];
__device__ half  g_kin[BB * SS * DD];
__device__ half  g_vin[BB * SS * DD];
__device__ half  g_Wqh[DD * DD];
__device__ half  g_Wkh[DD * DD];
__device__ half  g_Wvh[DD * DD];
__device__ half  g_Woh[DD * DD];
__device__ half  g_Qh[BB * SS * DD];
__device__ half  g_Kh[BB * SS * DD];
__device__ half  g_Vh[BB * SS * DD];
__device__ half  g_ctxh[BB * SS * DD];

// ---------------------------------------------------------------------------
// Helpers
// ---------------------------------------------------------------------------
__device__ __forceinline__ void mma_f16(float* d, const uint32_t* a, const uint32_t* b) {
    asm volatile(
        "mma.sync.aligned.m16n8k16.row.col.f32.f16.f16.f32 "
        "{%0,%1,%2,%3}, {%4,%5,%6,%7}, {%8,%9}, {%0,%1,%2,%3};"
        : "+f"(d[0]), "+f"(d[1]), "+f"(d[2]), "+f"(d[3])
        : "r"(a[0]), "r"(a[1]), "r"(a[2]), "r"(a[3]), "r"(b[0]), "r"(b[1]));
}
__device__ __forceinline__ void ldsm_x4(uint32_t& r0, uint32_t& r1, uint32_t& r2,
                                        uint32_t& r3, uint32_t addr) {
    asm volatile("ldmatrix.sync.aligned.m8n8.x4.shared.b16 {%0,%1,%2,%3}, [%4];"
                 : "=r"(r0), "=r"(r1), "=r"(r2), "=r"(r3) : "r"(addr));
}
__device__ __forceinline__ void ldsm_x4_t(uint32_t& r0, uint32_t& r1, uint32_t& r2,
                                          uint32_t& r3, uint32_t addr) {
    asm volatile("ldmatrix.sync.aligned.m8n8.x4.trans.shared.b16 {%0,%1,%2,%3}, [%4];"
                 : "=r"(r0), "=r"(r1), "=r"(r2), "=r"(r3) : "r"(addr));
}
__device__ __forceinline__ uint32_t smem_u32(const void* p) {
    uint32_t a;
    asm("{ .reg .u64 t; cvta.to.shared.u64 t, %1; cvt.u32.u64 %0, t; }"
        : "=r"(a) : "l"(p));
    return a;
}
__device__ __forceinline__ uint32_t pack_h2(float a, float b) {
    __half2 h = __floats2half2_rn(a, b);
    return *reinterpret_cast<uint32_t*>(&h);
}
__device__ __forceinline__ void cp16(uint32_t dst, const void* src) {
    asm volatile("cp.async.cg.shared.global [%0], [%1], 16;" :: "r"(dst), "l"(src));
}
__device__ __forceinline__ void cp_commit() {
    asm volatile("cp.async.commit_group;" ::: "memory");
}
template <int N>
__device__ __forceinline__ void cp_wait() {
    asm volatile("cp.async.wait_group %0;" :: "n"(N) : "memory");
}

// ===========================================================================
// Convert kernel: fp32 -> fp16 for q,k,v inputs and Wq,Wk,Wv,Wo
// ===========================================================================
__global__ __launch_bounds__(256)
void convert_kernel(const float4* q, const float4* k, const float4* v,
                    const float4* wq, const float4* wk, const float4* wv,
                    const float4* wo,
                    uint2* qh, uint2* kh, uint2* vh,
                    uint2* wqh, uint2* wkh, uint2* wvh, uint2* woh) {
    const int NI = BB * SS * DD / 4;   // 524288
    const int NW = DD * DD / 4;        // 65536
    int i = blockIdx.x * 256 + threadIdx.x;
    const float4* src; uint2* dst; int off;
    if (i < NI)                   { src = q;  dst = qh;  off = i; }
    else if (i < 2 * NI)          { src = k;  dst = kh;  off = i - NI; }
    else if (i < 3 * NI)          { src = v;  dst = vh;  off = i - 2 * NI; }
    else if (i < 3 * NI + NW)     { src = wq; dst = wqh; off = i - 3 * NI; }
    else if (i < 3 * NI + 2 * NW) { src = wk; dst = wkh; off = i - 3 * NI - NW; }
    else if (i < 3 * NI + 3 * NW) { src = wv; dst = wvh; off = i - 3 * NI - 2 * NW; }
    else                          { src = wo; dst = woh; off = i - 3 * NI - 3 * NW; }
    float4 x = src[off];
    dst[off] = make_uint2(pack_h2(x.x, x.y), pack_h2(x.z, x.w));
}

// ===========================================================================
// Shared GEMM mainloop (half inputs, cp.async 4-stage, BK=32, 128x128 tile).
// Epilogue differs: gemm3_h -> half C with scale; gemm_out_h -> float C.
// ===========================================================================
struct GemmFrag { float acc[2][8][4]; };

__device__ __forceinline__
void gemm_mainloop(const half* __restrict__ A, const half* __restrict__ W,
                   int M, int N, int K, int m0, int n0,
                   uint32_t sm_base, GemmFrag& f) {
    const int tid = threadIdx.x;
    const int warp = tid >> 5;
    const int lane = tid & 31;
    const int wm = warp & 3;
    const int wn = warp >> 2;

    auto issue_stage = [&](int kc, int s) {
        const uint32_t sa = sm_base + (uint32_t)(s * 9472) * 2;
        const uint32_t sw = sa + 5120 * 2;
#pragma unroll
        for (int t = 0; t < 2; t++) {
            int idx = tid + t * 256;
            int row = idx >> 2, c4 = idx & 3;
            cp16(sa + (uint32_t)(row * 40 + c4 * 8) * 2,
                 A + (size_t)(m0 + row) * K + kc * 32 + c4 * 8);
        }
#pragma unroll
        for (int t = 0; t < 2; t++) {
            int idx = tid + t * 256;
            int row = idx >> 4, c16 = idx & 15;
            cp16(sw + (uint32_t)(row * 136 + c16 * 8) * 2,
                 W + (size_t)(kc * 32 + row) * N + n0 + c16 * 8);
        }
        cp_commit();
    };

#pragma unroll
    for (int mi = 0; mi < 2; mi++)
#pragma unroll
        for (int nj = 0; nj < 8; nj++)
#pragma unroll
            for (int c = 0; c < 4; c++) f.acc[mi][nj][c] = 0.0f;

    issue_stage(0, 0);
    issue_stage(1, 1);

    const int nk = K / 32;
    for (int kc = 0; kc < nk; kc++) {
        const int s = kc & 3;
        if (kc + 2 < nk) { issue_stage(kc + 2, (kc + 2) & 3); cp_wait<2>(); }
        else if (kc + 1 < nk) { cp_wait<1>(); }
        else { cp_wait<0>(); }
        __syncthreads();

        const uint32_t a_base = sm_base + (uint32_t)(s * 9472) * 2;
        const uint32_t w_base = a_base + 5120 * 2;
#pragma unroll
        for (int ks = 0; ks < 2; ks++) {
            const int kb = ks * 16;
            uint32_t af[2][4];
#pragma unroll
            for (int mi = 0; mi < 2; mi++) {
                const int row = wm * 32 + mi * 16 + (lane & 15);
                const int col = kb + 8 * (lane >> 4);
                ldsm_x4(af[mi][0], af[mi][1], af[mi][2], af[mi][3],
                        a_base + (uint32_t)(row * 40 + col) * 2);
            }
#pragma unroll
            for (int nj2 = 0; nj2 < 4; nj2++) {
                const int row = kb + (lane & 7) + (((lane >> 3) & 1) * 8);
                const int col = wn * 64 + nj2 * 16 + (((lane >> 4) & 1) * 8);
                uint32_t b0r, b1r, b2r, b3r;
                ldsm_x4_t(b0r, b1r, b2r, b3r, w_base + (uint32_t)(row * 136 + col) * 2);
                uint32_t bb0[2] = {b0r, b1r}, bb1[2] = {b2r, b3r};
                mma_f16(f.acc[0][2 * nj2], af[0], bb0);
                mma_f16(f.acc[0][2 * nj2 + 1], af[0], bb1);
                mma_f16(f.acc[1][2 * nj2], af[1], bb0);
                mma_f16(f.acc[1][2 * nj2 + 1], af[1], bb1);
            }
        }
    }
}

// Fused Q/K/V projections (half out; z==0 scaled by 1/8)
__global__ __launch_bounds__(256, 2)
void gemm3_h(const half* A0, const half* A1, const half* A2,
             const half* W0, const half* W1, const half* W2,
             const float* b0, const float* b1, const float* b2,
             half* C0, half* C1, half* C2, int M, int N, int K) {
    extern __shared__ half smh[];
    const int z = blockIdx.z;
    const half* A = (z == 0) ? A0 : (z == 1) ? A1 : A2;
    const half* W = (z == 0) ? W0 : (z == 1) ? W1 : W2;
    const float* bias = (z == 0) ? b0 : (z == 1) ? b1 : b2;
    half* C = (z == 0) ? C0 : (z == 1) ? C1 : C2;
    const float scale = (z == 0) ? 0.125f : 1.0f;

    const int m0 = blockIdx.x * 128, n0 = blockIdx.y * 128;
    GemmFrag f;
    gemm_mainloop(A, W, M, N, K, m0, n0, smem_u32(smh), f);

    const int warp = threadIdx.x >> 5, lane = threadIdx.x & 31;
    const int g = lane >> 2, tg = lane & 3;
    const int wm = warp & 3, wn = warp >> 2;
#pragma unroll
    for (int mi = 0; mi < 2; mi++) {
        const int rb = m0 + wm * 32 + mi * 16;
#pragma unroll
        for (int nj = 0; nj < 8; nj++) {
            const int colb = n0 + wn * 64 + nj * 8 + 2 * tg;
            const float2 bv = *reinterpret_cast<const float2*>(bias + colb);
            *reinterpret_cast<uint32_t*>(C + (size_t)(rb + g) * N + colb) =
                pack_h2((f.acc[mi][nj][0] + bv.x) * scale, (f.acc[mi][nj][1] + bv.y) * scale);
            *reinterpret_cast<uint32_t*>(C + (size_t)(rb + g + 8) * N + colb) =
                pack_h2((f.acc[mi][nj][2] + bv.x) * scale, (f.acc[mi][nj][3] + bv.y) * scale);
        }
    }
}

// Output projection (half in, float out)
__global__ __launch_bounds__(256, 2)
void gemm_out_h(const half* __restrict__ A, const half* __restrict__ W,
                const float* __restrict__ bias, float* __restrict__ C,
                int M, int N, int K) {
    extern __shared__ half smh[];
    const int m0 = blockIdx.x * 128, n0 = blockIdx.y * 128;
    GemmFrag f;
    gemm_mainloop(A, W, M, N, K, m0, n0, smem_u32(smh), f);

    const int warp = threadIdx.x >> 5, lane = threadIdx.x & 31;
    const int g = lane >> 2, tg = lane & 3;
    const int wm = warp & 3, wn = warp >> 2;
#pragma unroll
    for (int mi = 0; mi < 2; mi++) {
        const int rb = m0 + wm * 32 + mi * 16;
#pragma unroll
        for (int nj = 0; nj < 8; nj++) {
            const int colb = n0 + wn * 64 + nj * 8 + 2 * tg;
            const float2 bv = *reinterpret_cast<const float2*>(bias + colb);
            *reinterpret_cast<float2*>(C + (size_t)(rb + g) * N + colb) =
                make_float2(f.acc[mi][nj][0] + bv.x, f.acc[mi][nj][1] + bv.y);
            *reinterpret_cast<float2*>(C + (size_t)(rb + g + 8) * N + colb) =
                make_float2(f.acc[mi][nj][2] + bv.x, f.acc[mi][nj][3] + bv.y);
        }
    }
}

// ===========================================================================
// Fused flash attention — fp16 mma, register-resident P (C-frag == A-frag),
// cp.async K/V 3-stage ring, deferred l-reduction. ctx written as half.
// smem (halfs): Q[128][72] + 3 x (K[64][72] + V[64][72]).
// ===========================================================================
__global__ __launch_bounds__(256, 2)
void attn_kernel(const half* __restrict__ Qg, const half* __restrict__ Kg,
                 const half* __restrict__ Vg, const float* __restrict__ structure,
                 half* __restrict__ ctx) {
    extern __shared__ half smh[];
    const uint32_t qs_base = smem_u32(smh);

    const int tid = threadIdx.x;
    const int warp = tid >> 5;
    const int lane = tid & 31;
    const int g = lane >> 2;
    const int tg = lane & 3;
    const int q0 = blockIdx.x * 128;
    const int h = blockIdx.y;
    const int b = blockIdx.z;
    const int rq = warp * 16;
    const size_t baseQ = ((size_t)b * SS + q0) * DD + h * 64;

    auto issue_kv = [&](int kt, int s) {
        const size_t baseK = ((size_t)b * SS + kt * 64) * DD + h * 64;
        const uint32_t kb = qs_base + (uint32_t)(9216 + s * 9216) * 2;
        const uint32_t vb = kb + 4608 * 2;
#pragma unroll
        for (int t = 0; t < 2; t++) {
            int idx = tid + t * 256;
            int row = idx >> 3, c8 = idx & 7;
            cp16(kb + (uint32_t)(row * 72 + c8 * 8) * 2,
                 Kg + baseK + (size_t)row * DD + c8 * 8);
        }
#pragma unroll
        for (int t = 0; t < 2; t++) {
            int idx = tid + t * 256;
            int row = idx >> 3, c8 = idx & 7;
            cp16(vb + (uint32_t)(row * 72 + c8 * 8) * 2,
                 Vg + baseK + (size_t)row * DD + c8 * 8);
        }
        cp_commit();
    };

    issue_kv(0, 0);
#pragma unroll
    for (int t = 0; t < 4; t++) {
        int idx = tid + t * 256;
        int row = idx >> 3, c8 = idx & 7;
        cp16(qs_base + (uint32_t)(row * 72 + c8 * 8) * 2,
             Qg + baseQ + (size_t)row * DD + c8 * 8);
    }
    cp_commit();
    cp_wait<0>();
    __syncthreads();

    // Preload Q fragments (persist in registers all kernel)
    uint32_t qf[4][4];
#pragma unroll
    for (int ks = 0; ks < 4; ks++) {
        const int row = rq + (lane & 15);
        const int col = ks * 16 + 8 * (lane >> 4);
        ldsm_x4(qf[ks][0], qf[ks][1], qf[ks][2], qf[ks][3],
                qs_base + (uint32_t)(row * 72 + col) * 2);
    }

    float m_[2] = {-1e30f, -1e30f};
    float l_[2] = {0.0f, 0.0f};   // per-lane partial sums (quad-reduced at end)
    float oacc[8][4];
#pragma unroll
    for (int nj = 0; nj < 8; nj++)
#pragma unroll
        for (int c = 0; c < 4; c++) oacc[nj][c] = 0.0f;

    for (int kt = 0; kt < SS / 64; kt++) {
        const int s = kt % 3;
        const int k0g = kt * 64;

        // Structure bias -> score accumulators
        float sacc[8][4];
#pragma unroll
        for (int nj = 0; nj < 8; nj++) {
            const int colb = k0g + nj * 8 + 2 * tg;
            const float2 s0 = *reinterpret_cast<const float2*>(
                structure + ((size_t)b * SS + q0 + rq + g) * SS + colb);
            const float2 s1 = *reinterpret_cast<const float2*>(
                structure + ((size_t)b * SS + q0 + rq + g + 8) * SS + colb);
            sacc[nj][0] = s0.x;
            sacc[nj][1] = s0.y;
            sacc[nj][2] = s1.x;
            sacc[nj][3] = s1.y;
        }

        if (kt + 1 < SS / 64) { issue_kv(kt + 1, (kt + 1) % 3); cp_wait<1>(); }
        else { cp_wait<0>(); }
        __syncthreads();

        const uint32_t ks_base = qs_base + (uint32_t)(9216 + s * 9216) * 2;
        const uint32_t vs_base = ks_base + 4608 * 2;

        // --- QK^T ---
#pragma unroll
        for (int ks = 0; ks < 4; ks++) {
            const int kb = ks * 16;
#pragma unroll
            for (int nj2 = 0; nj2 < 4; nj2++) {
                const int row = nj2 * 16 + (lane & 7) + (((lane >> 4) & 1) * 8);
                const int col = kb + (((lane >> 3) & 1) * 8);
                uint32_t b0r, b1r, b2r, b3r;
                ldsm_x4(b0r, b1r, b2r, b3r, ks_base + (uint32_t)(row * 72 + col) * 2);
                uint32_t bb0[2] = {b0r, b1r}, bb1[2] = {b2r, b3r};
                mma_f16(sacc[2 * nj2], qf[ks], bb0);
                mma_f16(sacc[2 * nj2 + 1], qf[ks], bb1);
            }
        }

        // --- Online softmax (max quad-reduced; sum kept per-lane) ---
#pragma unroll
        for (int h2 = 0; h2 < 2; h2++) {
            float mx = -1e30f;
#pragma unroll
            for (int nj = 0; nj < 8; nj++)
                mx = fmaxf(mx, fmaxf(sacc[nj][2 * h2], sacc[nj][2 * h2 + 1]));
            mx = fmaxf(mx, __shfl_xor_sync(0xffffffffu, mx, 1));
            mx = fmaxf(mx, __shfl_xor_sync(0xffffffffu, mx, 2));

            const float mn = fmaxf(m_[h2], mx);
            const float al = __expf(m_[h2] - mn);
            float rs = 0.0f;
#pragma unroll
            for (int nj = 0; nj < 8; nj++) {
                float p0 = __expf(sacc[nj][2 * h2] - mn);
                float p1 = __expf(sacc[nj][2 * h2 + 1] - mn);
                sacc[nj][2 * h2] = p0;
                sacc[nj][2 * h2 + 1] = p1;
                rs += p0 + p1;
            }
            l_[h2] = l_[h2] * al + rs;
            m_[h2] = mn;
#pragma unroll
            for (int nj = 0; nj < 8; nj++) {
                oacc[nj][2 * h2] *= al;
                oacc[nj][2 * h2 + 1] *= al;
            }
        }

        // --- PV with register-resident P: C-frag of QK^T == A-frag of PV ---
#pragma unroll
        for (int ks = 0; ks < 4; ks++) {
            uint32_t pf[4];
            pf[0] = pack_h2(sacc[2 * ks][0],     sacc[2 * ks][1]);
            pf[1] = pack_h2(sacc[2 * ks][2],     sacc[2 * ks][3]);
            pf[2] = pack_h2(sacc[2 * ks + 1][0], sacc[2 * ks + 1][1]);
            pf[3] = pack_h2(sacc[2 * ks + 1][2], sacc[2 * ks + 1][3]);
            const int cb = ks * 16;
#pragma unroll
            for (int db2 = 0; db2 < 4; db2++) {
                const int row = cb + (lane & 7) + (((lane >> 3) & 1) * 8);
                const int col = db2 * 16 + (((lane >> 4) & 1) * 8);
                uint32_t b0r, b1r, b2r, b3r;
                ldsm_x4_t(b0r, b1r, b2r, b3r, vs_base + (uint32_t)(row * 72 + col) * 2);
                uint32_t bb0[2] = {b0r, b1r}, bb1[2] = {b2r, b3r};
                mma_f16(oacc[2 * db2], pf, bb0);
                mma_f16(oacc[2 * db2 + 1], pf, bb1);
            }
        }
    }

    // Final l reduction across the quad, then normalize + write half ctx
#pragma unroll
    for (int h2 = 0; h2 < 2; h2++) {
        l_[h2] += __shfl_xor_sync(0xffffffffu, l_[h2], 1);
        l_[h2] += __shfl_xor_sync(0xffffffffu, l_[h2], 2);
    }
    const float inv0 = 1.0f / l_[0];
    const float inv1 = 1.0f / l_[1];
#pragma unroll
    for (int nj = 0; nj < 8; nj++) {
        const int colb = nj * 8 + 2 * tg;
        *reinterpret_cast<uint32_t*>(ctx + baseQ + (size_t)(rq + g) * DD + colb) =
            pack_h2(oacc[nj][0] * inv0, oacc[nj][1] * inv0);
        *reinterpret_cast<uint32_t*>(ctx + baseQ + (size_t)(rq + g + 8) * DD + colb) =
            pack_h2(oacc[nj][2] * inv1, oacc[nj][3] * inv1);
    }
}

// ===========================================================================
// kernel_launch
// ===========================================================================
extern "C" void kernel_launch(void* const* d_in, const int* in_sizes, int n_in,
                              void* d_out, int out_size) {
    const float* q   = (const float*)d_in[0];
    const float* k   = (const float*)d_in[1];
    const float* v   = (const float*)d_in[2];
    const float* str = (const float*)d_in[3];
    const float* Wq  = (const float*)d_in[4];
    const float* bq  = (const float*)d_in[5];
    const float* Wk  = (const float*)d_in[6];
    const float* bk  = (const float*)d_in[7];
    const float* Wv  = (const float*)d_in[8];
    const float* bv  = (const float*)d_in[9];
    const float* Wo  = (const float*)d_in[10];
    const float* bo  = (const float*)d_in[11];
    float* out = (float*)d_out;

    half *qin, *kin, *vin, *Wqh, *Wkh, *Wvh, *Woh, *Qh, *Kh, *Vh, *Ctxh;
    cudaGetSymbolAddress((void**)&qin, g_qin);
    cudaGetSymbolAddress((void**)&kin, g_kin);
    cudaGetSymbolAddress((void**)&vin, g_vin);
    cudaGetSymbolAddress((void**)&Wqh, g_Wqh);
    cudaGetSymbolAddress((void**)&Wkh, g_Wkh);
    cudaGetSymbolAddress((void**)&Wvh, g_Wvh);
    cudaGetSymbolAddress((void**)&Woh, g_Woh);
    cudaGetSymbolAddress((void**)&Qh, g_Qh);
    cudaGetSymbolAddress((void**)&Kh, g_Kh);
    cudaGetSymbolAddress((void**)&Vh, g_Vh);
    cudaGetSymbolAddress((void**)&Ctxh, g_ctxh);

    const int M = BB * SS;   // 4096
    const int N = DD;        // 512
    const int K = DD;        // 512

    // 1) convert inputs + all weights to fp16
    const int NI = BB * SS * DD / 4, NW = DD * DD / 4;
    convert_kernel<<<(3 * NI + 4 * NW) / 256, 256>>>(
        (const float4*)q, (const float4*)k, (const float4*)v,
        (const float4*)Wq, (const float4*)Wk, (const float4*)Wv, (const float4*)Wo,
        (uint2*)qin, (uint2*)kin, (uint2*)vin,
        (uint2*)Wqh, (uint2*)Wkh, (uint2*)Wvh, (uint2*)Woh);

    // 2) fused Q/K/V projections
    const int gsm = 4 * 9472 * (int)sizeof(half);   // 75776 B
    cudaFuncSetAttribute(gemm3_h, cudaFuncAttributeMaxDynamicSharedMemorySize, gsm);
    dim3 g3(M / 128, N / 128, 3);
    gemm3_h<<<g3, 256, gsm>>>(qin, kin, vin, Wqh, Wkh, Wvh,
                              bq, bk, bv, Qh, Kh, Vh, M, N, K);

    // 3) attention (half ctx out)
    const int att_smem = (9216 + 3 * 9216) * (int)sizeof(half);   // 73728 B
    cudaFuncSetAttribute(attn_kernel, cudaFuncAttributeMaxDynamicSharedMemorySize,
                         att_smem);
    dim3 att_grid(SS / 128, HH, BB);
    attn_kernel<<<att_grid, 256, att_smem>>>(Qh, Kh, Vh, str, Ctxh);

    // 4) output projection (half in, float out, cp.async pipeline)
    cudaFuncSetAttribute(gemm_out_h, cudaFuncAttributeMaxDynamicSharedMemorySize, gsm);
    dim3 gemm_grid(M / 128, N / 128);
    gemm_out_h<<<gemm_grid, 256, gsm>>>(Ctxh, Woh, bo, out, M, N, K);
}